// round 11
// baseline (speedup 1.0000x reference)
#include <cuda_runtime.h>
#include <cuda_fp16.h>
#include <stdint.h>
#include <math.h>

#define T_TOK 1024
#define H_DIM 2048
#define F_DIM 4096
#define E_EXP 8
#define ROWS_CAP 3072
#define MTILES (ROWS_CAP / 128)   // 24
#define KSPLIT 4

// A tiles: fp16, 128 rows x 32 halves, padded to 40 halves (20 words) per row
#define AP_W 20
#define AS_W (128 * AP_W)         // 2560 words
// GEMM1 B stages: f32, 32 rows x 64 cols, padded to 68 words
#define BP13 68
#define B13_W (32 * BP13)         // 2176 words
#define STG13_W (AS_W + 2 * B13_W)          // 6912 words
// fp16 converted B (ping-pong), pitch 26 words per column
#define BT_P 26
#define BT13_MAT (64 * BT_P)                // 1664 words
#define BT13_BUF (2 * BT13_MAT)             // 3328 words
#define BT13_OFF (3 * STG13_W)              // 20736
#define SMEM13 ((BT13_OFF + 2 * BT13_BUF) * 4)   // 109568 B
// GEMM2 B stages: f32, 32 rows x 128 cols, padded to 132 words
#define BP2 132
#define B2_W (32 * BP2)           // 4224 words
#define STG2_W (AS_W + B2_W)                // 6784 words
#define BT2_BUF (128 * BT_P)                // 3328 words
#define BT2_OFF (3 * STG2_W)                // 20352
#define SMEM2 ((BT2_OFF + 2 * BT2_BUF) * 4)      // 108032 B

// ---------------- scratch ----------------
__device__ __align__(256) __half g_X[(size_t)ROWS_CAP * H_DIM];
__device__ __align__(256) __half g_A[(size_t)ROWS_CAP * F_DIM];
__device__ __align__(256) float  g_Y[(size_t)KSPLIT * ROWS_CAP * H_DIM];
__device__ int   g_off[E_EXP + 1];
__device__ int   g_tile_e[MTILES];
__device__ int   g_rows[ROWS_CAP];
__device__ float g_rw[ROWS_CAP];
__device__ int   g_pos[T_TOK * 2];
__device__ int   g_te[T_TOK * 2];
__device__ float g_tw[T_TOK * 2];

__device__ __forceinline__ float silu_f(float v) { return v / (1.0f + expf(-v)); }

__device__ __forceinline__ uint32_t smem_u32(const void* p) {
    uint32_t a;
    asm("{ .reg .u64 t; cvta.to.shared.u64 t, %1; cvt.u32.u64 %0, t; }" : "=r"(a) : "l"(p));
    return a;
}
__device__ __forceinline__ void cp16(uint32_t dst, const void* src) {
    asm volatile("cp.async.cg.shared.global [%0], [%1], 16;" :: "r"(dst), "l"(src));
}
#define CP_COMMIT() asm volatile("cp.async.commit_group;" ::: "memory")
#define CP_WAIT1()  asm volatile("cp.async.wait_group 1;" ::: "memory")
#define CP_WAIT0()  asm volatile("cp.async.wait_group 0;" ::: "memory")

// pack two f32 -> half2 reg: low = first arg, high = second
__device__ __forceinline__ uint32_t pack_h2(float lo, float hi) {
    uint32_t d;
    asm("cvt.rn.f16x2.f32 %0, %1, %2;" : "=r"(d) : "f"(hi), "f"(lo));
    return d;
}

__device__ __forceinline__ void ldsm4(uint32_t& r0, uint32_t& r1, uint32_t& r2, uint32_t& r3,
                                      uint32_t addr) {
    asm volatile("ldmatrix.sync.aligned.m8n8.x4.shared.b16 {%0,%1,%2,%3}, [%4];"
        : "=r"(r0), "=r"(r1), "=r"(r2), "=r"(r3) : "r"(addr));
}

__device__ __forceinline__ void mma_f16(float& c0, float& c1, float& c2, float& c3,
                                        uint32_t a0, uint32_t a1, uint32_t a2, uint32_t a3,
                                        uint32_t b0, uint32_t b1) {
    asm volatile(
        "mma.sync.aligned.m16n8k16.row.col.f32.f16.f16.f32 "
        "{%0,%1,%2,%3}, {%4,%5,%6,%7}, {%8,%9}, {%0,%1,%2,%3};\n"
        : "+f"(c0), "+f"(c1), "+f"(c2), "+f"(c3)
        : "r"(a0), "r"(a1), "r"(a2), "r"(a3), "r"(b0), "r"(b1));
}

// ------------------------------- routing -----------------------------------
__global__ void gate_kernel(const float* __restrict__ x, const float* __restrict__ wg) {
    int t = blockIdx.x * (blockDim.x >> 5) + (threadIdx.x >> 5);
    int lane = threadIdx.x & 31;
    if (t >= T_TOK) return;
    const float* xr = x + (size_t)t * H_DIM;
    float acc[E_EXP];
#pragma unroll
    for (int e = 0; e < E_EXP; e++) acc[e] = 0.0f;
    for (int h = lane; h < H_DIM; h += 32) {
        float xv = xr[h];
        const float* wr = wg + (size_t)h * E_EXP;
#pragma unroll
        for (int e = 0; e < E_EXP; e++) acc[e] += xv * wr[e];
    }
#pragma unroll
    for (int e = 0; e < E_EXP; e++)
#pragma unroll
        for (int o = 16; o > 0; o >>= 1) acc[e] += __shfl_xor_sync(0xffffffffu, acc[e], o);
    if (lane == 0) {
        int i0 = 0; float v0 = acc[0];
#pragma unroll
        for (int e = 1; e < E_EXP; e++) if (acc[e] > v0) { v0 = acc[e]; i0 = e; }
        int i1 = -1; float v1 = -INFINITY;
#pragma unroll
        for (int e = 0; e < E_EXP; e++) if (e != i0 && acc[e] > v1) { v1 = acc[e]; i1 = e; }
        float w0 = 1.0f / (1.0f + expf(v1 - v0));
        g_te[2 * t] = i0;     g_tw[2 * t] = w0;
        g_te[2 * t + 1] = i1; g_tw[2 * t + 1] = 1.0f - w0;
    }
}

__global__ void route_scatter_kernel() {
    __shared__ int scnt[E_EXP], soff[E_EXP + 1], sfill[E_EXP];
    int tid = threadIdx.x;
    if (tid < E_EXP) { scnt[tid] = 0; sfill[tid] = 0; }
    __syncthreads();
    for (int i = tid; i < 2 * T_TOK; i += 256) atomicAdd(&scnt[g_te[i]], 1);
    __syncthreads();
    if (tid == 0) {
        int o = 0;
#pragma unroll
        for (int e = 0; e < E_EXP; e++) { soff[e] = o; o += (scnt[e] + 127) & ~127; }
        soff[E_EXP] = o;
#pragma unroll
        for (int e = 0; e <= E_EXP; e++) g_off[e] = soff[e];
    }
    __syncthreads();
    if (tid < MTILES) {
        int e = -1;
#pragma unroll
        for (int ee = 0; ee < E_EXP; ee++)
            if (tid * 128 >= soff[ee] && tid * 128 < soff[ee + 1]) e = ee;
        g_tile_e[tid] = e;
    }
    for (int r = tid; r < ROWS_CAP; r += 256) {
        g_rows[r] = 0;
        g_rw[r] = 0.0f;
    }
    __syncthreads();
    for (int t = tid; t < T_TOK; t += 256) {
#pragma unroll
        for (int s = 0; s < 2; s++) {
            int e = g_te[2 * t + s];
            int r = soff[e] + atomicAdd(&sfill[e], 1);
            g_rows[r] = t;
            g_rw[r] = g_tw[2 * t + s];
            g_pos[2 * t + s] = r;
        }
    }
}

// gather x rows -> fp16 g_X
__global__ void gather_kernel(const float* __restrict__ x) {
    int idx = blockIdx.x * blockDim.x + threadIdx.x;
    int r = idx >> 9;
    if (r >= g_off[E_EXP]) return;
    int h = (idx & 511) << 2;
    float4 v = *reinterpret_cast<const float4*>(x + (size_t)g_rows[r] * H_DIM + h);
    *reinterpret_cast<__half2*>(g_X + (size_t)r * H_DIM + h) = __floats2half2_rn(v.x, v.y);
    *reinterpret_cast<__half2*>(g_X + (size_t)r * H_DIM + h + 2) = __floats2half2_rn(v.z, v.w);
}

// ---------------------------------------------------------------------------
// GEMM1 fused: block 128x64x32, 8 warps (4M x 2N, R8-verified layout).
// Pipelined self-owned B convert (tile i+1) overlapped with mma (tile i).
// ---------------------------------------------------------------------------
__global__ __launch_bounds__(256, 2) void gemm13_kernel(const float* __restrict__ w1,
                                                        const float* __restrict__ w3) {
    extern __shared__ uint32_t smem[];

    const int my = blockIdx.y;
    const int e = g_tile_e[my];
    if (e < 0) return;

    const int tid = threadIdx.x;
    const int warp = tid >> 5;
    const int lane = tid & 31;
    const int wm = warp & 3;
    const int wn = warp >> 2;
    const int g = lane >> 2;
    const int tg = lane & 3;

    const int bm = my * 128;
    const int bn = blockIdx.x * 64;

    const float* B1g = w1 + (size_t)e * H_DIM * F_DIM;
    const float* B3g = w3 + (size_t)e * H_DIM * F_DIM;
    const uint32_t sbase = smem_u32(smem);

    // A staging: 2 slots per thread (unchanged from R8)
    const __half* a_src[2];
    uint32_t da[2];
#pragma unroll
    for (int i = 0; i < 2; i++) {
        int slot = tid + i * 256;
        int r = slot >> 2;
        int q = slot & 3;
        a_src[i] = g_X + (size_t)(bm + r) * H_DIM + q * 8;
        da[i] = (uint32_t)(r * AP_W * 4 + q * 16);
    }
    // B staging: self-owned row pairs (2o, 2o+1) at quad sq
    const int so = tid >> 4;          // 0..15 row pair
    const int sq = tid & 15;          // 0..15 quad (4 cols)
    const float* b1p0 = B1g + (size_t)(2 * so) * F_DIM + bn + 4 * sq;
    const float* b1p1 = b1p0 + F_DIM;
    const float* b3p0 = B3g + (size_t)(2 * so) * F_DIM + bn + 4 * sq;
    const float* b3p1 = b3p0 + F_DIM;
    const uint32_t db10 = (uint32_t)(AS_W + (2 * so) * BP13 + 4 * sq) * 4u;
    const uint32_t db11 = (uint32_t)(AS_W + (2 * so + 1) * BP13 + 4 * sq) * 4u;
    const uint32_t db30 = db10 + B13_W * 4u;
    const uint32_t db31 = db11 + B13_W * 4u;
    // convert dest word index for this row pair (R9-verified mapping)
    const int cn = 8 * (so >> 3) + 2 * (so & 3) + ((so >> 2) & 1);

    float c1[2][4][4], c3[2][4][4];
#pragma unroll
    for (int mi = 0; mi < 2; mi++)
#pragma unroll
        for (int ni = 0; ni < 4; ni++)
#pragma unroll
            for (int q = 0; q < 4; q++) { c1[mi][ni][q] = 0.0f; c3[mi][ni][q] = 0.0f; }

    const int kt = H_DIM / 32;  // 64

    // prologue: issue tiles 0,1
#pragma unroll
    for (int it = 0; it < 2; it++) {
        uint32_t ab = sbase + (uint32_t)it * (STG13_W * 4);
        size_t k0 = (size_t)it * 32;
        cp16(ab + da[0], a_src[0] + k0);
        cp16(ab + da[1], a_src[1] + k0);
        cp16(ab + db10, b1p0 + k0 * F_DIM);
        cp16(ab + db11, b1p1 + k0 * F_DIM);
        cp16(ab + db30, b3p0 + k0 * F_DIM);
        cp16(ab + db31, b3p1 + k0 * F_DIM);
        CP_COMMIT();
    }
    // convert own tile-0 B data (own cp.async only -> wait suffices, no barrier)
    CP_WAIT1();
    {
        const float* st = (const float*)(smem + AS_W);
        uint32_t* d1 = smem + BT13_OFF;              // buffer 0
        uint32_t* d3 = d1 + BT13_MAT;
        float4 r0 = *reinterpret_cast<const float4*>(st + (2 * so) * BP13 + 4 * sq);
        float4 r1 = *reinterpret_cast<const float4*>(st + (2 * so + 1) * BP13 + 4 * sq);
        d1[(4 * sq + 0) * BT_P + cn] = pack_h2(r0.x, r1.x);
        d1[(4 * sq + 1) * BT_P + cn] = pack_h2(r0.y, r1.y);
        d1[(4 * sq + 2) * BT_P + cn] = pack_h2(r0.z, r1.z);
        d1[(4 * sq + 3) * BT_P + cn] = pack_h2(r0.w, r1.w);
        const float* st3 = st + B13_W;
        float4 s0 = *reinterpret_cast<const float4*>(st3 + (2 * so) * BP13 + 4 * sq);
        float4 s1 = *reinterpret_cast<const float4*>(st3 + (2 * so + 1) * BP13 + 4 * sq);
        d3[(4 * sq + 0) * BT_P + cn] = pack_h2(s0.x, s1.x);
        d3[(4 * sq + 1) * BT_P + cn] = pack_h2(s0.y, s1.y);
        d3[(4 * sq + 2) * BT_P + cn] = pack_h2(s0.z, s1.z);
        d3[(4 * sq + 3) * BT_P + cn] = pack_h2(s0.w, s1.w);
    }

    // ldmatrix mapping (R9-verified): row = lane&15, k-half = lane>>4
    const int arow = wm * 32 + (lane & 15);
    const int akoff = (lane >> 4) * 8;   // halves

    for (int it = 0; it < kt; it++) {
        const int stg = it % 3;
        CP_WAIT1();            // all own tiles <= it complete
        __syncthreads();       // publish copies <= it and Bt[it&1]; slot safety

        if (it + 2 < kt) {
            int nt = it + 2;
            uint32_t ab = sbase + (uint32_t)(nt % 3) * (STG13_W * 4);
            size_t k0 = (size_t)nt * 32;
            cp16(ab + da[0], a_src[0] + k0);
            cp16(ab + da[1], a_src[1] + k0);
            cp16(ab + db10, b1p0 + k0 * F_DIM);
            cp16(ab + db11, b1p1 + k0 * F_DIM);
            cp16(ab + db30, b3p0 + k0 * F_DIM);
            cp16(ab + db31, b3p1 + k0 * F_DIM);
            CP_COMMIT();
            CP_WAIT1();        // own tiles <= it+1 complete
        } else {
            CP_WAIT0();
        }

        // convert own B of tile it+1 into Bt[(it+1)&1] (overlaps with mma below)
        if (it + 1 < kt) {
            const int ns = (it + 1) % 3;
            const float* st = (const float*)(smem + ns * STG13_W + AS_W);
            uint32_t* d1 = smem + BT13_OFF + ((it + 1) & 1) * BT13_BUF;
            uint32_t* d3 = d1 + BT13_MAT;
            float4 r0 = *reinterpret_cast<const float4*>(st + (2 * so) * BP13 + 4 * sq);
            float4 r1 = *reinterpret_cast<const float4*>(st + (2 * so + 1) * BP13 + 4 * sq);
            d1[(4 * sq + 0) * BT_P + cn] = pack_h2(r0.x, r1.x);
            d1[(4 * sq + 1) * BT_P + cn] = pack_h2(r0.y, r1.y);
            d1[(4 * sq + 2) * BT_P + cn] = pack_h2(r0.z, r1.z);
            d1[(4 * sq + 3) * BT_P + cn] = pack_h2(r0.w, r1.w);
            const float* st3 = st + B13_W;
            float4 s0 = *reinterpret_cast<const float4*>(st3 + (2 * so) * BP13 + 4 * sq);
            float4 s1 = *reinterpret_cast<const float4*>(st3 + (2 * so + 1) * BP13 + 4 * sq);
            d3[(4 * sq + 0) * BT_P + cn] = pack_h2(s0.x, s1.x);
            d3[(4 * sq + 1) * BT_P + cn] = pack_h2(s0.y, s1.y);
            d3[(4 * sq + 2) * BT_P + cn] = pack_h2(s0.z, s1.z);
            d3[(4 * sq + 3) * BT_P + cn] = pack_h2(s0.w, s1.w);
        }

        // mma on tile it
        const uint32_t abase = sbase + (uint32_t)stg * (STG13_W * 4);
        const uint32_t* Bt1 = smem + BT13_OFF + (it & 1) * BT13_BUF;
        const uint32_t* Bt3 = Bt1 + BT13_MAT;
#pragma unroll
        for (int ks = 0; ks < 2; ks++) {
            uint32_t a[2][4];
#pragma unroll
            for (int mi = 0; mi < 2; mi++) {
                uint32_t ad = abase + (uint32_t)((arow + mi * 16) * 40 + ks * 16 + akoff) * 2;
                ldsm4(a[mi][0], a[mi][1], a[mi][2], a[mi][3], ad);
            }
#pragma unroll
            for (int ni = 0; ni < 4; ni++) {
                const int col = wn * 32 + ni * 8 + g;
                uint2 b1v = *reinterpret_cast<const uint2*>(Bt1 + col * BT_P + ks * 8 + 2 * tg);
                uint2 b3v = *reinterpret_cast<const uint2*>(Bt3 + col * BT_P + ks * 8 + 2 * tg);
#pragma unroll
                for (int mi = 0; mi < 2; mi++) {
                    mma_f16(c1[mi][ni][0], c1[mi][ni][1], c1[mi][ni][2], c1[mi][ni][3],
                            a[mi][0], a[mi][1], a[mi][2], a[mi][3], b1v.x, b1v.y);
                    mma_f16(c3[mi][ni][0], c3[mi][ni][1], c3[mi][ni][2], c3[mi][ni][3],
                            a[mi][0], a[mi][1], a[mi][2], a[mi][3], b3v.x, b3v.y);
                }
            }
        }
    }

    // epilogue (R8-verified, 4M x 2N)
    const int r_base = bm + wm * 32;
    const int c_base = bn + wn * 32;
#pragma unroll
    for (int mi = 0; mi < 2; mi++) {
        int r0 = r_base + mi * 16 + g;
        float wa = g_rw[r0];
        float wb = g_rw[r0 + 8];
        size_t o0 = (size_t)r0 * F_DIM;
        size_t o1 = (size_t)(r0 + 8) * F_DIM;
#pragma unroll
        for (int ni = 0; ni < 4; ni++) {
            int cl = c_base + ni * 8 + 2 * tg;
            __half2 v0 = __floats2half2_rn(silu_f(c1[mi][ni][0]) * c3[mi][ni][0] * wa,
                                           silu_f(c1[mi][ni][1]) * c3[mi][ni][1] * wa);
            __half2 v1 = __floats2half2_rn(silu_f(c1[mi][ni][2]) * c3[mi][ni][2] * wb,
                                           silu_f(c1[mi][ni][3]) * c3[mi][ni][3] * wb);
            *reinterpret_cast<__half2*>(g_A + o0 + cl) = v0;
            *reinterpret_cast<__half2*>(g_A + o1 + cl) = v1;
        }
    }
}

// ---------------------------------------------------------------------------
// GEMM2: block 128x128x32, K-split 4, 8 warps (4M x 2N, R8-verified layout).
// Same pipelined convert scheme.
// ---------------------------------------------------------------------------
__global__ __launch_bounds__(256, 2) void gemm2_kernel(const float* __restrict__ w2) {
    extern __shared__ uint32_t smem[];

    const int my = blockIdx.y;
    const int e = g_tile_e[my];
    if (e < 0) return;
    const int z = blockIdx.z;

    const int tid = threadIdx.x;
    const int warp = tid >> 5;
    const int lane = tid & 31;
    const int wm = warp & 3;
    const int wn = warp >> 2;
    const int g = lane >> 2;
    const int tg = lane & 3;

    const int bm = my * 128;
    const int bn = blockIdx.x * 128;
    const int kseg = F_DIM / KSPLIT;   // 1024

    const __half* Abase = g_A + (size_t)z * kseg;
    const float* Bbase = w2 + (size_t)e * F_DIM * H_DIM + (size_t)z * kseg * H_DIM;
    const uint32_t sbase = smem_u32(smem);

    const __half* a_src[2];
    uint32_t da[2];
#pragma unroll
    for (int i = 0; i < 2; i++) {
        int slot = tid + i * 256;
        int r = slot >> 2;
        int q = slot & 3;
        a_src[i] = Abase + (size_t)(bm + r) * F_DIM + q * 8;
        da[i] = (uint32_t)(r * AP_W * 4 + q * 16);
    }
    // B staging: thread owns rows (2o, 2o+1) at quads sq and sq+16
    const int so = tid >> 4;
    const int sq = tid & 15;
    const float* bp0 = Bbase + (size_t)(2 * so) * H_DIM + bn + 4 * sq;
    const float* bp1 = bp0 + H_DIM;
    const float* bp2 = bp0 + 64;          // quad sq+16
    const float* bp3 = bp1 + 64;
    const uint32_t dbw0 = (uint32_t)(AS_W + (2 * so) * BP2 + 4 * sq) * 4u;
    const uint32_t dbw1 = (uint32_t)(AS_W + (2 * so + 1) * BP2 + 4 * sq) * 4u;
    const uint32_t dbw2 = dbw0 + 64 * 4u;
    const uint32_t dbw3 = dbw1 + 64 * 4u;
    const int cn = 8 * (so >> 3) + 2 * (so & 3) + ((so >> 2) & 1);

    float c[2][8][4];
#pragma unroll
    for (int mi = 0; mi < 2; mi++)
#pragma unroll
        for (int ni = 0; ni < 8; ni++)
#pragma unroll
            for (int q = 0; q < 4; q++) c[mi][ni][q] = 0.0f;

    const int kt = kseg / 32;   // 32

#pragma unroll
    for (int it = 0; it < 2; it++) {
        uint32_t ab = sbase + (uint32_t)it * (STG2_W * 4);
        size_t k0 = (size_t)it * 32;
        cp16(ab + da[0], a_src[0] + k0);
        cp16(ab + da[1], a_src[1] + k0);
        cp16(ab + dbw0, bp0 + k0 * H_DIM);
        cp16(ab + dbw1, bp1 + k0 * H_DIM);
        cp16(ab + dbw2, bp2 + k0 * H_DIM);
        cp16(ab + dbw3, bp3 + k0 * H_DIM);
        CP_COMMIT();
    }
    CP_WAIT1();
    {
        const float* st = (const float*)(smem + AS_W);
        uint32_t* d = smem + BT2_OFF;
#pragma unroll
        for (int qg = 0; qg < 2; qg++) {
            int cq = 4 * sq + qg * 64;
            float4 r0 = *reinterpret_cast<const float4*>(st + (2 * so) * BP2 + cq);
            float4 r1 = *reinterpret_cast<const float4*>(st + (2 * so + 1) * BP2 + cq);
            d[(cq + 0) * BT_P + cn] = pack_h2(r0.x, r1.x);
            d[(cq + 1) * BT_P + cn] = pack_h2(r0.y, r1.y);
            d[(cq + 2) * BT_P + cn] = pack_h2(r0.z, r1.z);
            d[(cq + 3) * BT_P + cn] = pack_h2(r0.w, r1.w);
        }
    }

    const int arow = wm * 32 + (lane & 15);
    const int akoff = (lane >> 4) * 8;

    for (int it = 0; it < kt; it++) {
        const int stg = it % 3;
        CP_WAIT1();
        __syncthreads();

        if (it + 2 < kt) {
            int nt = it + 2;
            uint32_t ab = sbase + (uint32_t)(nt % 3) * (STG2_W * 4);
            size_t k0 = (size_t)nt * 32;
            cp16(ab + da[0], a_src[0] + k0);
            cp16(ab + da[1], a_src[1] + k0);
            cp16(ab + dbw0, bp0 + k0 * H_DIM);
            cp16(ab + dbw1, bp1 + k0 * H_DIM);
            cp16(ab + dbw2, bp2 + k0 * H_DIM);
            cp16(ab + dbw3, bp3 + k0 * H_DIM);
            CP_COMMIT();
            CP_WAIT1();
        } else {
            CP_WAIT0();
        }

        if (it + 1 < kt) {
            const int ns = (it + 1) % 3;
            const float* st = (const float*)(smem + ns * STG2_W + AS_W);
            uint32_t* d = smem + BT2_OFF + ((it + 1) & 1) * BT2_BUF;
#pragma unroll
            for (int qg = 0; qg < 2; qg++) {
                int cq = 4 * sq + qg * 64;
                float4 r0 = *reinterpret_cast<const float4*>(st + (2 * so) * BP2 + cq);
                float4 r1 = *reinterpret_cast<const float4*>(st + (2 * so + 1) * BP2 + cq);
                d[(cq + 0) * BT_P + cn] = pack_h2(r0.x, r1.x);
                d[(cq + 1) * BT_P + cn] = pack_h2(r0.y, r1.y);
                d[(cq + 2) * BT_P + cn] = pack_h2(r0.z, r1.z);
                d[(cq + 3) * BT_P + cn] = pack_h2(r0.w, r1.w);
            }
        }

        const uint32_t abase = sbase + (uint32_t)stg * (STG2_W * 4);
        const uint32_t* Bt = smem + BT2_OFF + (it & 1) * BT2_BUF;
#pragma unroll
        for (int ks = 0; ks < 2; ks++) {
            uint32_t a[2][4];
#pragma unroll
            for (int mi = 0; mi < 2; mi++) {
                uint32_t ad = abase + (uint32_t)((arow + mi * 16) * 40 + ks * 16 + akoff) * 2;
                ldsm4(a[mi][0], a[mi][1], a[mi][2], a[mi][3], ad);
            }
#pragma unroll
            for (int ni = 0; ni < 8; ni++) {
                const int col = wn * 64 + ni * 8 + g;
                uint2 bv = *reinterpret_cast<const uint2*>(Bt + col * BT_P + ks * 8 + 2 * tg);
#pragma unroll
                for (int mi = 0; mi < 2; mi++)
                    mma_f16(c[mi][ni][0], c[mi][ni][1], c[mi][ni][2], c[mi][ni][3],
                            a[mi][0], a[mi][1], a[mi][2], a[mi][3], bv.x, bv.y);
            }
        }
    }

    float* Yp = g_Y + (size_t)z * ((size_t)ROWS_CAP * H_DIM);
    const int r_base = bm + wm * 32;
    const int c_base = bn + wn * 64;
#pragma unroll
    for (int mi = 0; mi < 2; mi++) {
        int r0 = r_base + mi * 16 + g;
        size_t o0 = (size_t)r0 * H_DIM;
        size_t o1 = (size_t)(r0 + 8) * H_DIM;
#pragma unroll
        for (int ni = 0; ni < 8; ni++) {
            int cl = c_base + ni * 8 + 2 * tg;
            *reinterpret_cast<float2*>(Yp + o0 + cl) = make_float2(c[mi][ni][0], c[mi][ni][1]);
            *reinterpret_cast<float2*>(Yp + o1 + cl) = make_float2(c[mi][ni][2], c[mi][ni][3]);
        }
    }
}

// out[t] = sum over (slot, kslice) — fixed order, deterministic
__global__ void combine_kernel(float* __restrict__ out) {
    int i = blockIdx.x * blockDim.x + threadIdx.x;
    int t = i >> 9;
    int h = (i & 511) << 2;
    size_t r0 = (size_t)g_pos[2 * t] * H_DIM + h;
    size_t r1 = (size_t)g_pos[2 * t + 1] * H_DIM + h;
    const size_t SL = (size_t)ROWS_CAP * H_DIM;
    float4 s0 = make_float4(0.f, 0.f, 0.f, 0.f);
    float4 s1 = make_float4(0.f, 0.f, 0.f, 0.f);
#pragma unroll
    for (int zz = 0; zz < KSPLIT; zz++) {
        float4 a = *reinterpret_cast<const float4*>(g_Y + zz * SL + r0);
        float4 b = *reinterpret_cast<const float4*>(g_Y + zz * SL + r1);
        s0.x += a.x; s0.y += a.y; s0.z += a.z; s0.w += a.w;
        s1.x += b.x; s1.y += b.y; s1.z += b.z; s1.w += b.w;
    }
    *reinterpret_cast<float4*>(out + (size_t)t * H_DIM + h) =
        make_float4(s0.x + s1.x, s0.y + s1.y, s0.z + s1.z, s0.w + s1.w);
}

extern "C" void kernel_launch(void* const* d_in, const int* in_sizes, int n_in,
                              void* d_out, int out_size) {
    const float* x  = (const float*)d_in[0];
    const float* wg = (const float*)d_in[1];
    const float* w1 = (const float*)d_in[2];
    const float* w3 = (const float*)d_in[3];
    const float* w2 = (const float*)d_in[4];
    float* out = (float*)d_out;

    cudaFuncSetAttribute(gemm13_kernel, cudaFuncAttributeMaxDynamicSharedMemorySize, SMEM13);
    cudaFuncSetAttribute(gemm2_kernel, cudaFuncAttributeMaxDynamicSharedMemorySize, SMEM2);

    gate_kernel<<<T_TOK / 8, 256>>>(x, wg);
    route_scatter_kernel<<<1, 256>>>();
    gather_kernel<<<ROWS_CAP * 512 / 256, 256>>>(x);

    dim3 g1(F_DIM / 64, MTILES);
    gemm13_kernel<<<g1, 256, SMEM13>>>(w1, w3);

    dim3 g2(H_DIM / 128, MTILES, KSPLIT);
    gemm2_kernel<<<g2, 256, SMEM2>>>(w2);

    combine_kernel<<<(T_TOK * H_DIM / 4) / 256, 256>>>(out);
}

// round 12
// speedup vs baseline: 1.2195x; 1.2195x over previous
#include <cuda_runtime.h>
#include <cuda_fp16.h>
#include <stdint.h>
#include <math.h>

#define T_TOK 1024
#define H_DIM 2048
#define F_DIM 4096
#define E_EXP 8
#define ROWS_CAP 3072
#define MTILES (ROWS_CAP / 128)   // 24
#define KSPLIT 4

// A tiles: fp16, 128 rows x 32 halves, padded to 40 halves (20 words) per row
#define AP_W 20
#define AS_W (128 * AP_W)         // 2560 words; stages are A-only now
// fp16 B tile buffers (Bt): [j][col] layout, j = 0..15 k-pair words
// gemm13: 2 matrices x 64 cols, pitch 68 words
#define PJ13 68
#define BT13_MAT (16 * PJ13)      // 1088 words
#define BT13_BUF (2 * BT13_MAT)   // 2176 words (w1 + w3)
#define BT13_OFF (3 * AS_W)       // 7680
#define SMEM13 ((BT13_OFF + 2 * BT13_BUF) * 4)   // 48128 B
// gemm2: 1 matrix x 128 cols, pitch 132 words
#define PJ2 132
#define BT2_BUF (16 * PJ2)        // 2112 words
#define BT2_OFF (3 * AS_W)        // 7680
#define SMEM2 ((BT2_OFF + 2 * BT2_BUF) * 4)      // 47616 B

// ---------------- scratch ----------------
__device__ __align__(256) __half g_X[(size_t)ROWS_CAP * H_DIM];
__device__ __align__(256) __half g_A[(size_t)ROWS_CAP * F_DIM];
__device__ __align__(256) float  g_Y[(size_t)KSPLIT * ROWS_CAP * H_DIM];
__device__ int   g_off[E_EXP + 1];
__device__ int   g_tile_e[MTILES];
__device__ int   g_rows[ROWS_CAP];
__device__ float g_rw[ROWS_CAP];
__device__ int   g_pos[T_TOK * 2];
__device__ int   g_te[T_TOK * 2];
__device__ float g_tw[T_TOK * 2];

__device__ __forceinline__ float silu_f(float v) { return v / (1.0f + expf(-v)); }

__device__ __forceinline__ uint32_t smem_u32(const void* p) {
    uint32_t a;
    asm("{ .reg .u64 t; cvta.to.shared.u64 t, %1; cvt.u32.u64 %0, t; }" : "=r"(a) : "l"(p));
    return a;
}
__device__ __forceinline__ void cp16(uint32_t dst, const void* src) {
    asm volatile("cp.async.cg.shared.global [%0], [%1], 16;" :: "r"(dst), "l"(src));
}
#define CP_COMMIT() asm volatile("cp.async.commit_group;" ::: "memory")
#define CP_WAIT1()  asm volatile("cp.async.wait_group 1;" ::: "memory")
#define CP_WAIT0()  asm volatile("cp.async.wait_group 0;" ::: "memory")

// pack two f32 -> half2 reg: low = first arg, high = second
__device__ __forceinline__ uint32_t pack_h2(float lo, float hi) {
    uint32_t d;
    asm("cvt.rn.f16x2.f32 %0, %1, %2;" : "=r"(d) : "f"(hi), "f"(lo));
    return d;
}

__device__ __forceinline__ void ldsm4(uint32_t& r0, uint32_t& r1, uint32_t& r2, uint32_t& r3,
                                      uint32_t addr) {
    asm volatile("ldmatrix.sync.aligned.m8n8.x4.shared.b16 {%0,%1,%2,%3}, [%4];"
        : "=r"(r0), "=r"(r1), "=r"(r2), "=r"(r3) : "r"(addr));
}

__device__ __forceinline__ void mma_f16(float& c0, float& c1, float& c2, float& c3,
                                        uint32_t a0, uint32_t a1, uint32_t a2, uint32_t a3,
                                        uint32_t b0, uint32_t b1) {
    asm volatile(
        "mma.sync.aligned.m16n8k16.row.col.f32.f16.f16.f32 "
        "{%0,%1,%2,%3}, {%4,%5,%6,%7}, {%8,%9}, {%0,%1,%2,%3};\n"
        : "+f"(c0), "+f"(c1), "+f"(c2), "+f"(c3)
        : "r"(a0), "r"(a1), "r"(a2), "r"(a3), "r"(b0), "r"(b1));
}

// ------------------------------- routing -----------------------------------
__global__ void gate_kernel(const float* __restrict__ x, const float* __restrict__ wg) {
    int t = blockIdx.x * (blockDim.x >> 5) + (threadIdx.x >> 5);
    int lane = threadIdx.x & 31;
    if (t >= T_TOK) return;
    const float* xr = x + (size_t)t * H_DIM;
    float acc[E_EXP];
#pragma unroll
    for (int e = 0; e < E_EXP; e++) acc[e] = 0.0f;
    for (int h = lane; h < H_DIM; h += 32) {
        float xv = xr[h];
        const float* wr = wg + (size_t)h * E_EXP;
#pragma unroll
        for (int e = 0; e < E_EXP; e++) acc[e] += xv * wr[e];
    }
#pragma unroll
    for (int e = 0; e < E_EXP; e++)
#pragma unroll
        for (int o = 16; o > 0; o >>= 1) acc[e] += __shfl_xor_sync(0xffffffffu, acc[e], o);
    if (lane == 0) {
        int i0 = 0; float v0 = acc[0];
#pragma unroll
        for (int e = 1; e < E_EXP; e++) if (acc[e] > v0) { v0 = acc[e]; i0 = e; }
        int i1 = -1; float v1 = -INFINITY;
#pragma unroll
        for (int e = 0; e < E_EXP; e++) if (e != i0 && acc[e] > v1) { v1 = acc[e]; i1 = e; }
        float w0 = 1.0f / (1.0f + expf(v1 - v0));
        g_te[2 * t] = i0;     g_tw[2 * t] = w0;
        g_te[2 * t + 1] = i1; g_tw[2 * t + 1] = 1.0f - w0;
    }
}

__global__ void route_scatter_kernel() {
    __shared__ int scnt[E_EXP], soff[E_EXP + 1], sfill[E_EXP];
    int tid = threadIdx.x;
    if (tid < E_EXP) { scnt[tid] = 0; sfill[tid] = 0; }
    __syncthreads();
    for (int i = tid; i < 2 * T_TOK; i += 256) atomicAdd(&scnt[g_te[i]], 1);
    __syncthreads();
    if (tid == 0) {
        int o = 0;
#pragma unroll
        for (int e = 0; e < E_EXP; e++) { soff[e] = o; o += (scnt[e] + 127) & ~127; }
        soff[E_EXP] = o;
#pragma unroll
        for (int e = 0; e <= E_EXP; e++) g_off[e] = soff[e];
    }
    __syncthreads();
    if (tid < MTILES) {
        int e = -1;
#pragma unroll
        for (int ee = 0; ee < E_EXP; ee++)
            if (tid * 128 >= soff[ee] && tid * 128 < soff[ee + 1]) e = ee;
        g_tile_e[tid] = e;
    }
    for (int r = tid; r < ROWS_CAP; r += 256) {
        g_rows[r] = 0;
        g_rw[r] = 0.0f;
    }
    __syncthreads();
    for (int t = tid; t < T_TOK; t += 256) {
#pragma unroll
        for (int s = 0; s < 2; s++) {
            int e = g_te[2 * t + s];
            int r = soff[e] + atomicAdd(&sfill[e], 1);
            g_rows[r] = t;
            g_rw[r] = g_tw[2 * t + s];
            g_pos[2 * t + s] = r;
        }
    }
}

// gather x rows -> fp16 g_X
__global__ void gather_kernel(const float* __restrict__ x) {
    int idx = blockIdx.x * blockDim.x + threadIdx.x;
    int r = idx >> 9;
    if (r >= g_off[E_EXP]) return;
    int h = (idx & 511) << 2;
    float4 v = *reinterpret_cast<const float4*>(x + (size_t)g_rows[r] * H_DIM + h);
    *reinterpret_cast<__half2*>(g_X + (size_t)r * H_DIM + h) = __floats2half2_rn(v.x, v.y);
    *reinterpret_cast<__half2*>(g_X + (size_t)r * H_DIM + h + 2) = __floats2half2_rn(v.z, v.w);
}

// ---------------------------------------------------------------------------
// Bt layout proof: word j of column col holds pack(B[2so], B[2so+1]) where
// so = row-pair. Consumer needs word j = 8ks+2tg+i = rows (16ks+2tg+8i, +1),
// i.e. so = 8ks+tg+4i. Then cn(so)=8(so>>3)+2(so&3)+((so>>2)&1) = 8ks+2tg+i = j.
// Producer writes at cn(so); consumer reads j — identical. (cn map R9-verified.)
// ---------------------------------------------------------------------------

// GEMM1 fused: block 128x64x32, 8 warps (4M x 2N, R8-verified layout).
// A: cp.async 3-stage fp16 + ldmatrix. B: LDG f32 (1 tile ahead) -> cvt -> STS
// fp16 Bt ping-pong; fragments are conflict-free LDS.32 of packed fp16.
__global__ __launch_bounds__(256, 2) void gemm13_kernel(const float* __restrict__ w1,
                                                        const float* __restrict__ w3) {
    extern __shared__ uint32_t smem[];

    const int my = blockIdx.y;
    const int e = g_tile_e[my];
    if (e < 0) return;

    const int tid = threadIdx.x;
    const int warp = tid >> 5;
    const int lane = tid & 31;
    const int wm = warp & 3;
    const int wn = warp >> 2;
    const int g = lane >> 2;
    const int tg = lane & 3;

    const int bm = my * 128;
    const int bn = blockIdx.x * 64;

    const float* B1g = w1 + (size_t)e * H_DIM * F_DIM;
    const float* B3g = w3 + (size_t)e * H_DIM * F_DIM;
    const uint32_t sbase = smem_u32(smem);

    // A staging (cp.async): 512 16B slots, 2 per thread
    const __half* a_src[2];
    uint32_t da[2];
#pragma unroll
    for (int i = 0; i < 2; i++) {
        int slot = tid + i * 256;
        int r = slot >> 2;
        int q = slot & 3;
        a_src[i] = g_X + (size_t)(bm + r) * H_DIM + q * 8;
        da[i] = (uint32_t)(r * AP_W * 4 + q * 16);
    }
    // B ownership: row pair (2so, 2so+1), quad sq (cols 4sq..4sq+3)
    const int so = tid >> 4;
    const int sq = tid & 15;
    const float* b1p0 = B1g + (size_t)(2 * so) * F_DIM + bn + 4 * sq;
    const float* b1p1 = b1p0 + F_DIM;
    const float* b3p0 = B3g + (size_t)(2 * so) * F_DIM + bn + 4 * sq;
    const float* b3p1 = b3p0 + F_DIM;
    const int cn = 8 * (so >> 3) + 2 * (so & 3) + ((so >> 2) & 1);
    const int sts_off = cn * PJ13 + 4 * sq;

    float c1[2][4][4], c3[2][4][4];
#pragma unroll
    for (int mi = 0; mi < 2; mi++)
#pragma unroll
        for (int ni = 0; ni < 4; ni++)
#pragma unroll
            for (int q = 0; q < 4; q++) { c1[mi][ni][q] = 0.0f; c3[mi][ni][q] = 0.0f; }

    const int kt = H_DIM / 32;  // 64

    // prologue: A stages for tiles 0,1; B regs for tile 0
#pragma unroll
    for (int it = 0; it < 2; it++) {
        uint32_t ab = sbase + (uint32_t)it * (AS_W * 4);
        size_t k0 = (size_t)it * 32;
        cp16(ab + da[0], a_src[0] + k0);
        cp16(ab + da[1], a_src[1] + k0);
        CP_COMMIT();
    }
    float4 r10 = *reinterpret_cast<const float4*>(b1p0);
    float4 r11 = *reinterpret_cast<const float4*>(b1p1);
    float4 r30 = *reinterpret_cast<const float4*>(b3p0);
    float4 r31 = *reinterpret_cast<const float4*>(b3p1);

    // ldmatrix mapping (R9/R11-verified): row = lane&15, k-half = lane>>4
    const int arow = wm * 32 + (lane & 15);
    const int akoff = (lane >> 4) * 8;   // halves

    for (int it = 0; it < kt; it++) {
        // STS: pack held regs (tile it) -> Bt[it&1]
        {
            uint32_t* d1 = smem + BT13_OFF + (it & 1) * BT13_BUF;
            uint32_t* d3 = d1 + BT13_MAT;
            uint4 s1 = make_uint4(pack_h2(r10.x, r11.x), pack_h2(r10.y, r11.y),
                                  pack_h2(r10.z, r11.z), pack_h2(r10.w, r11.w));
            uint4 s3 = make_uint4(pack_h2(r30.x, r31.x), pack_h2(r30.y, r31.y),
                                  pack_h2(r30.z, r31.z), pack_h2(r30.w, r31.w));
            *reinterpret_cast<uint4*>(d1 + sts_off) = s1;
            *reinterpret_cast<uint4*>(d3 + sts_off) = s3;
        }
        if (it == kt - 1) { CP_WAIT0(); } else { CP_WAIT1(); }
        __syncthreads();   // publishes Bt[it&1] + A copies <= it; slot safety

        if (it + 2 < kt) {
            uint32_t ab = sbase + (uint32_t)((it + 2) % 3) * (AS_W * 4);
            size_t k0 = (size_t)(it + 2) * 32;
            cp16(ab + da[0], a_src[0] + k0);
            cp16(ab + da[1], a_src[1] + k0);
            CP_COMMIT();
        }
        // LDG B for tile it+1 (clamped; unused at tail)
        {
            int nb = (it + 1 < kt) ? it + 1 : 0;
            size_t ko = (size_t)nb * 32 * F_DIM;
            r10 = *reinterpret_cast<const float4*>(b1p0 + ko);
            r11 = *reinterpret_cast<const float4*>(b1p1 + ko);
            r30 = *reinterpret_cast<const float4*>(b3p0 + ko);
            r31 = *reinterpret_cast<const float4*>(b3p1 + ko);
        }

        // mma tile it
        const uint32_t abase = sbase + (uint32_t)(it % 3) * (AS_W * 4);
        const uint32_t* Bt1 = smem + BT13_OFF + (it & 1) * BT13_BUF;
        const uint32_t* Bt3 = Bt1 + BT13_MAT;
#pragma unroll
        for (int ks = 0; ks < 2; ks++) {
            uint32_t a[2][4];
#pragma unroll
            for (int mi = 0; mi < 2; mi++) {
                uint32_t ad = abase + (uint32_t)((arow + mi * 16) * 40 + ks * 16 + akoff) * 2;
                ldsm4(a[mi][0], a[mi][1], a[mi][2], a[mi][3], ad);
            }
            const int jb = ks * 8 + 2 * tg;
#pragma unroll
            for (int ni = 0; ni < 4; ni++) {
                const int col = wn * 32 + ni * 8 + g;
                uint32_t b10 = Bt1[jb * PJ13 + col];
                uint32_t b11 = Bt1[(jb + 1) * PJ13 + col];
                uint32_t b30 = Bt3[jb * PJ13 + col];
                uint32_t b31 = Bt3[(jb + 1) * PJ13 + col];
#pragma unroll
                for (int mi = 0; mi < 2; mi++) {
                    mma_f16(c1[mi][ni][0], c1[mi][ni][1], c1[mi][ni][2], c1[mi][ni][3],
                            a[mi][0], a[mi][1], a[mi][2], a[mi][3], b10, b11);
                    mma_f16(c3[mi][ni][0], c3[mi][ni][1], c3[mi][ni][2], c3[mi][ni][3],
                            a[mi][0], a[mi][1], a[mi][2], a[mi][3], b30, b31);
                }
            }
        }
    }

    // epilogue (R8-verified, 4M x 2N)
    const int r_base = bm + wm * 32;
    const int c_base = bn + wn * 32;
#pragma unroll
    for (int mi = 0; mi < 2; mi++) {
        int r0 = r_base + mi * 16 + g;
        float wa = g_rw[r0];
        float wb = g_rw[r0 + 8];
        size_t o0 = (size_t)r0 * F_DIM;
        size_t o1 = (size_t)(r0 + 8) * F_DIM;
#pragma unroll
        for (int ni = 0; ni < 4; ni++) {
            int cl = c_base + ni * 8 + 2 * tg;
            __half2 v0 = __floats2half2_rn(silu_f(c1[mi][ni][0]) * c3[mi][ni][0] * wa,
                                           silu_f(c1[mi][ni][1]) * c3[mi][ni][1] * wa);
            __half2 v1 = __floats2half2_rn(silu_f(c1[mi][ni][2]) * c3[mi][ni][2] * wb,
                                           silu_f(c1[mi][ni][3]) * c3[mi][ni][3] * wb);
            *reinterpret_cast<__half2*>(g_A + o0 + cl) = v0;
            *reinterpret_cast<__half2*>(g_A + o1 + cl) = v1;
        }
    }
}

// ---------------------------------------------------------------------------
// GEMM2: block 128x128x32, K-split 4, 8 warps (4M x 2N). Same B scheme.
// ---------------------------------------------------------------------------
__global__ __launch_bounds__(256, 2) void gemm2_kernel(const float* __restrict__ w2) {
    extern __shared__ uint32_t smem[];

    const int my = blockIdx.y;
    const int e = g_tile_e[my];
    if (e < 0) return;
    const int z = blockIdx.z;

    const int tid = threadIdx.x;
    const int warp = tid >> 5;
    const int lane = tid & 31;
    const int wm = warp & 3;
    const int wn = warp >> 2;
    const int g = lane >> 2;
    const int tg = lane & 3;

    const int bm = my * 128;
    const int bn = blockIdx.x * 128;
    const int kseg = F_DIM / KSPLIT;   // 1024

    const __half* Abase = g_A + (size_t)z * kseg;
    const float* Bbase = w2 + (size_t)e * F_DIM * H_DIM + (size_t)z * kseg * H_DIM;
    const uint32_t sbase = smem_u32(smem);

    const __half* a_src[2];
    uint32_t da[2];
#pragma unroll
    for (int i = 0; i < 2; i++) {
        int slot = tid + i * 256;
        int r = slot >> 2;
        int q = slot & 3;
        a_src[i] = Abase + (size_t)(bm + r) * F_DIM + q * 8;
        da[i] = (uint32_t)(r * AP_W * 4 + q * 16);
    }
    const int so = tid >> 4;
    const int sq = tid & 15;
    const float* bp0 = Bbase + (size_t)(2 * so) * H_DIM + bn + 4 * sq;
    const float* bp1 = bp0 + H_DIM;
    const int cn = 8 * (so >> 3) + 2 * (so & 3) + ((so >> 2) & 1);
    const int sts0 = cn * PJ2 + 4 * sq;
    const int sts1 = sts0 + 64;

    float c[2][8][4];
#pragma unroll
    for (int mi = 0; mi < 2; mi++)
#pragma unroll
        for (int ni = 0; ni < 8; ni++)
#pragma unroll
            for (int q = 0; q < 4; q++) c[mi][ni][q] = 0.0f;

    const int kt = kseg / 32;   // 32

#pragma unroll
    for (int it = 0; it < 2; it++) {
        uint32_t ab = sbase + (uint32_t)it * (AS_W * 4);
        size_t k0 = (size_t)it * 32;
        cp16(ab + da[0], a_src[0] + k0);
        cp16(ab + da[1], a_src[1] + k0);
        CP_COMMIT();
    }
    float4 ra0 = *reinterpret_cast<const float4*>(bp0);
    float4 ra1 = *reinterpret_cast<const float4*>(bp1);
    float4 rb0 = *reinterpret_cast<const float4*>(bp0 + 64);
    float4 rb1 = *reinterpret_cast<const float4*>(bp1 + 64);

    const int arow = wm * 32 + (lane & 15);
    const int akoff = (lane >> 4) * 8;

    for (int it = 0; it < kt; it++) {
        {
            uint32_t* d = smem + BT2_OFF + (it & 1) * BT2_BUF;
            uint4 s0 = make_uint4(pack_h2(ra0.x, ra1.x), pack_h2(ra0.y, ra1.y),
                                  pack_h2(ra0.z, ra1.z), pack_h2(ra0.w, ra1.w));
            uint4 s1 = make_uint4(pack_h2(rb0.x, rb1.x), pack_h2(rb0.y, rb1.y),
                                  pack_h2(rb0.z, rb1.z), pack_h2(rb0.w, rb1.w));
            *reinterpret_cast<uint4*>(d + sts0) = s0;
            *reinterpret_cast<uint4*>(d + sts1) = s1;
        }
        if (it == kt - 1) { CP_WAIT0(); } else { CP_WAIT1(); }
        __syncthreads();

        if (it + 2 < kt) {
            uint32_t ab = sbase + (uint32_t)((it + 2) % 3) * (AS_W * 4);
            size_t k0 = (size_t)(it + 2) * 32;
            cp16(ab + da[0], a_src[0] + k0);
            cp16(ab + da[1], a_src[1] + k0);
            CP_COMMIT();
        }
        {
            int nb = (it + 1 < kt) ? it + 1 : 0;
            size_t ko = (size_t)nb * 32 * H_DIM;
            ra0 = *reinterpret_cast<const float4*>(bp0 + ko);
            ra1 = *reinterpret_cast<const float4*>(bp1 + ko);
            rb0 = *reinterpret_cast<const float4*>(bp0 + ko + 64);
            rb1 = *reinterpret_cast<const float4*>(bp1 + ko + 64);
        }

        const uint32_t abase = sbase + (uint32_t)(it % 3) * (AS_W * 4);
        const uint32_t* Bt = smem + BT2_OFF + (it & 1) * BT2_BUF;
#pragma unroll
        for (int ks = 0; ks < 2; ks++) {
            uint32_t a[2][4];
#pragma unroll
            for (int mi = 0; mi < 2; mi++) {
                uint32_t ad = abase + (uint32_t)((arow + mi * 16) * 40 + ks * 16 + akoff) * 2;
                ldsm4(a[mi][0], a[mi][1], a[mi][2], a[mi][3], ad);
            }
            const int jb = ks * 8 + 2 * tg;
#pragma unroll
            for (int ni = 0; ni < 8; ni++) {
                const int col = wn * 64 + ni * 8 + g;
                uint32_t b0 = Bt[jb * PJ2 + col];
                uint32_t b1 = Bt[(jb + 1) * PJ2 + col];
#pragma unroll
                for (int mi = 0; mi < 2; mi++)
                    mma_f16(c[mi][ni][0], c[mi][ni][1], c[mi][ni][2], c[mi][ni][3],
                            a[mi][0], a[mi][1], a[mi][2], a[mi][3], b0, b1);
            }
        }
    }

    float* Yp = g_Y + (size_t)z * ((size_t)ROWS_CAP * H_DIM);
    const int r_base = bm + wm * 32;
    const int c_base = bn + wn * 64;
#pragma unroll
    for (int mi = 0; mi < 2; mi++) {
        int r0 = r_base + mi * 16 + g;
        size_t o0 = (size_t)r0 * H_DIM;
        size_t o1 = (size_t)(r0 + 8) * H_DIM;
#pragma unroll
        for (int ni = 0; ni < 8; ni++) {
            int cl = c_base + ni * 8 + 2 * tg;
            *reinterpret_cast<float2*>(Yp + o0 + cl) = make_float2(c[mi][ni][0], c[mi][ni][1]);
            *reinterpret_cast<float2*>(Yp + o1 + cl) = make_float2(c[mi][ni][2], c[mi][ni][3]);
        }
    }
}

// out[t] = sum over (slot, kslice) — fixed order, deterministic
__global__ void combine_kernel(float* __restrict__ out) {
    int i = blockIdx.x * blockDim.x + threadIdx.x;
    int t = i >> 9;
    int h = (i & 511) << 2;
    size_t r0 = (size_t)g_pos[2 * t] * H_DIM + h;
    size_t r1 = (size_t)g_pos[2 * t + 1] * H_DIM + h;
    const size_t SL = (size_t)ROWS_CAP * H_DIM;
    float4 s0 = make_float4(0.f, 0.f, 0.f, 0.f);
    float4 s1 = make_float4(0.f, 0.f, 0.f, 0.f);
#pragma unroll
    for (int zz = 0; zz < KSPLIT; zz++) {
        float4 a = *reinterpret_cast<const float4*>(g_Y + zz * SL + r0);
        float4 b = *reinterpret_cast<const float4*>(g_Y + zz * SL + r1);
        s0.x += a.x; s0.y += a.y; s0.z += a.z; s0.w += a.w;
        s1.x += b.x; s1.y += b.y; s1.z += b.z; s1.w += b.w;
    }
    *reinterpret_cast<float4*>(out + (size_t)t * H_DIM + h) =
        make_float4(s0.x + s1.x, s0.y + s1.y, s0.z + s1.z, s0.w + s1.w);
}

extern "C" void kernel_launch(void* const* d_in, const int* in_sizes, int n_in,
                              void* d_out, int out_size) {
    const float* x  = (const float*)d_in[0];
    const float* wg = (const float*)d_in[1];
    const float* w1 = (const float*)d_in[2];
    const float* w3 = (const float*)d_in[3];
    const float* w2 = (const float*)d_in[4];
    float* out = (float*)d_out;

    cudaFuncSetAttribute(gemm13_kernel, cudaFuncAttributeMaxDynamicSharedMemorySize, SMEM13);
    cudaFuncSetAttribute(gemm2_kernel, cudaFuncAttributeMaxDynamicSharedMemorySize, SMEM2);

    gate_kernel<<<T_TOK / 8, 256>>>(x, wg);
    route_scatter_kernel<<<1, 256>>>();
    gather_kernel<<<ROWS_CAP * 512 / 256, 256>>>(x);

    dim3 g1(F_DIM / 64, MTILES);
    gemm13_kernel<<<g1, 256, SMEM13>>>(w1, w3);

    dim3 g2(H_DIM / 128, MTILES, KSPLIT);
    gemm2_kernel<<<g2, 256, SMEM2>>>(w2);

    combine_kernel<<<(T_TOK * H_DIM / 4) / 256, 256>>>(out);
}

// round 13
// speedup vs baseline: 1.3170x; 1.0799x over previous
#include <cuda_runtime.h>
#include <cuda_fp16.h>
#include <stdint.h>
#include <math.h>

#define T_TOK 1024
#define H_DIM 2048
#define F_DIM 4096
#define E_EXP 8
#define ROWS_CAP 3072
#define MTILES (ROWS_CAP / 128)   // 24
#define KSPLIT 4

// K-chunk = 64. A tiles: fp16, 128 rows x 64 halves, padded to 72 (36 words)
#define AP_W 36
#define AS_W (128 * AP_W)         // 4608 words
// GEMM1 B tiles: f32, 64 rows x 64 cols, padded to 68 words
#define BP13 68
#define B13_W (64 * BP13)         // 4352 words
#define STG13_W (AS_W + 2 * B13_W)          // 13312 words
#define SMEM13 (2 * STG13_W * 4)            // 106496 B
// GEMM2 B tiles: f32, 64 rows x 128 cols, padded to 132 words
#define BP2 132
#define B2_W (64 * BP2)           // 8448 words
#define STG2_W (AS_W + B2_W)                // 13056 words
#define SMEM2 (2 * STG2_W * 4)              // 104448 B

// ---------------- scratch ----------------
__device__ __align__(256) __half g_X[(size_t)ROWS_CAP * H_DIM];
__device__ __align__(256) __half g_A[(size_t)ROWS_CAP * F_DIM];
__device__ __align__(256) float  g_Y[(size_t)KSPLIT * ROWS_CAP * H_DIM];
__device__ int   g_off[E_EXP + 1];
__device__ int   g_tile_e[MTILES];
__device__ int   g_rows[ROWS_CAP];
__device__ float g_rw[ROWS_CAP];
__device__ int   g_pos[T_TOK * 2];
__device__ int   g_te[T_TOK * 2];
__device__ float g_tw[T_TOK * 2];

__device__ __forceinline__ float silu_f(float v) { return v / (1.0f + expf(-v)); }

__device__ __forceinline__ uint32_t smem_u32(const void* p) {
    uint32_t a;
    asm("{ .reg .u64 t; cvta.to.shared.u64 t, %1; cvt.u32.u64 %0, t; }" : "=r"(a) : "l"(p));
    return a;
}
__device__ __forceinline__ void cp16(uint32_t dst, const void* src) {
    asm volatile("cp.async.cg.shared.global [%0], [%1], 16;" :: "r"(dst), "l"(src));
}
#define CP_COMMIT() asm volatile("cp.async.commit_group;" ::: "memory")
#define CP_WAIT0()  asm volatile("cp.async.wait_group 0;" ::: "memory")

// pack two f32 -> half2 reg: low = first arg, high = second
__device__ __forceinline__ uint32_t pack_h2(float lo, float hi) {
    uint32_t d;
    asm("cvt.rn.f16x2.f32 %0, %1, %2;" : "=r"(d) : "f"(hi), "f"(lo));
    return d;
}

__device__ __forceinline__ void ldsm4(uint32_t& r0, uint32_t& r1, uint32_t& r2, uint32_t& r3,
                                      uint32_t addr) {
    asm volatile("ldmatrix.sync.aligned.m8n8.x4.shared.b16 {%0,%1,%2,%3}, [%4];"
        : "=r"(r0), "=r"(r1), "=r"(r2), "=r"(r3) : "r"(addr));
}

__device__ __forceinline__ void mma_f16(float& c0, float& c1, float& c2, float& c3,
                                        uint32_t a0, uint32_t a1, uint32_t a2, uint32_t a3,
                                        uint32_t b0, uint32_t b1) {
    asm volatile(
        "mma.sync.aligned.m16n8k16.row.col.f32.f16.f16.f32 "
        "{%0,%1,%2,%3}, {%4,%5,%6,%7}, {%8,%9}, {%0,%1,%2,%3};\n"
        : "+f"(c0), "+f"(c1), "+f"(c2), "+f"(c3)
        : "r"(a0), "r"(a1), "r"(a2), "r"(a3), "r"(b0), "r"(b1));
}

// ------------------------------- routing -----------------------------------
__global__ void gate_kernel(const float* __restrict__ x, const float* __restrict__ wg) {
    int t = blockIdx.x * (blockDim.x >> 5) + (threadIdx.x >> 5);
    int lane = threadIdx.x & 31;
    if (t >= T_TOK) return;
    const float* xr = x + (size_t)t * H_DIM;
    float acc[E_EXP];
#pragma unroll
    for (int e = 0; e < E_EXP; e++) acc[e] = 0.0f;
    for (int h = lane; h < H_DIM; h += 32) {
        float xv = xr[h];
        const float* wr = wg + (size_t)h * E_EXP;
#pragma unroll
        for (int e = 0; e < E_EXP; e++) acc[e] += xv * wr[e];
    }
#pragma unroll
    for (int e = 0; e < E_EXP; e++)
#pragma unroll
        for (int o = 16; o > 0; o >>= 1) acc[e] += __shfl_xor_sync(0xffffffffu, acc[e], o);
    if (lane == 0) {
        int i0 = 0; float v0 = acc[0];
#pragma unroll
        for (int e = 1; e < E_EXP; e++) if (acc[e] > v0) { v0 = acc[e]; i0 = e; }
        int i1 = -1; float v1 = -INFINITY;
#pragma unroll
        for (int e = 0; e < E_EXP; e++) if (e != i0 && acc[e] > v1) { v1 = acc[e]; i1 = e; }
        float w0 = 1.0f / (1.0f + expf(v1 - v0));
        g_te[2 * t] = i0;     g_tw[2 * t] = w0;
        g_te[2 * t + 1] = i1; g_tw[2 * t + 1] = 1.0f - w0;
    }
}

__global__ void route_scatter_kernel() {
    __shared__ int scnt[E_EXP], soff[E_EXP + 1], sfill[E_EXP];
    int tid = threadIdx.x;
    if (tid < E_EXP) { scnt[tid] = 0; sfill[tid] = 0; }
    __syncthreads();
    for (int i = tid; i < 2 * T_TOK; i += 256) atomicAdd(&scnt[g_te[i]], 1);
    __syncthreads();
    if (tid == 0) {
        int o = 0;
#pragma unroll
        for (int e = 0; e < E_EXP; e++) { soff[e] = o; o += (scnt[e] + 127) & ~127; }
        soff[E_EXP] = o;
#pragma unroll
        for (int e = 0; e <= E_EXP; e++) g_off[e] = soff[e];
    }
    __syncthreads();
    if (tid < MTILES) {
        int e = -1;
#pragma unroll
        for (int ee = 0; ee < E_EXP; ee++)
            if (tid * 128 >= soff[ee] && tid * 128 < soff[ee + 1]) e = ee;
        g_tile_e[tid] = e;
    }
    for (int r = tid; r < ROWS_CAP; r += 256) {
        g_rows[r] = 0;
        g_rw[r] = 0.0f;
    }
    __syncthreads();
    for (int t = tid; t < T_TOK; t += 256) {
#pragma unroll
        for (int s = 0; s < 2; s++) {
            int e = g_te[2 * t + s];
            int r = soff[e] + atomicAdd(&sfill[e], 1);
            g_rows[r] = t;
            g_rw[r] = g_tw[2 * t + s];
            g_pos[2 * t + s] = r;
        }
    }
}

// gather x rows -> fp16 g_X
__global__ void gather_kernel(const float* __restrict__ x) {
    int idx = blockIdx.x * blockDim.x + threadIdx.x;
    int r = idx >> 9;
    if (r >= g_off[E_EXP]) return;
    int h = (idx & 511) << 2;
    float4 v = *reinterpret_cast<const float4*>(x + (size_t)g_rows[r] * H_DIM + h);
    *reinterpret_cast<__half2*>(g_X + (size_t)r * H_DIM + h) = __floats2half2_rn(v.x, v.y);
    *reinterpret_cast<__half2*>(g_X + (size_t)r * H_DIM + h + 2) = __floats2half2_rn(v.z, v.w);
}

// ---------------------------------------------------------------------------
// GEMM1 fused (fp16 mma): C1 = g_X@w1[e], C3 = g_X@w3[e];
// g_A = fp16(silu(C1)*C3*rw). Block 128x64xK64, 8 warps (4M x 2N, R8 layout).
// 2-stage pipeline, one barrier per 64-K chunk (4 ks-steps per phase).
// ---------------------------------------------------------------------------
__global__ __launch_bounds__(256, 2) void gemm13_kernel(const float* __restrict__ w1,
                                                        const float* __restrict__ w3) {
    extern __shared__ uint32_t smem[];

    const int my = blockIdx.y;
    const int e = g_tile_e[my];
    if (e < 0) return;

    const int tid = threadIdx.x;
    const int warp = tid >> 5;
    const int lane = tid & 31;
    const int wm = warp & 3;
    const int wn = warp >> 2;
    const int g = lane >> 2;
    const int tg = lane & 3;

    const int bm = my * 128;
    const int bn = blockIdx.x * 64;

    const float* B1g = w1 + (size_t)e * H_DIM * F_DIM;
    const float* B3g = w3 + (size_t)e * H_DIM * F_DIM;
    const uint32_t sbase = smem_u32(smem);

    // A staging: 1024 16B slots (128 rows x 8), 4 per thread
    const __half* a_src[4];
    uint32_t da[4];
#pragma unroll
    for (int i = 0; i < 4; i++) {
        int slot = tid + i * 256;
        int r = slot >> 3;
        int q = slot & 7;
        a_src[i] = g_X + (size_t)(bm + r) * H_DIM + q * 8;
        da[i] = (uint32_t)(r * AP_W * 4 + q * 16);
    }
    // B staging: 1024 slots per matrix (64 rows x 16 quads), 4 per thread each
    const float* b1_src[4];
    const float* b3_src[4];
    uint32_t db[4];
#pragma unroll
    for (int i = 0; i < 4; i++) {
        int slot = tid + i * 256;
        int r = slot >> 4;
        int c4 = (slot & 15) << 2;
        b1_src[i] = B1g + (size_t)r * F_DIM + bn + c4;
        b3_src[i] = B3g + (size_t)r * F_DIM + bn + c4;
        db[i] = (uint32_t)(AS_W + r * BP13 + c4) * 4u;
    }

    float c1[2][4][4], c3[2][4][4];
#pragma unroll
    for (int mi = 0; mi < 2; mi++)
#pragma unroll
        for (int ni = 0; ni < 4; ni++)
#pragma unroll
            for (int q = 0; q < 4; q++) { c1[mi][ni][q] = 0.0f; c3[mi][ni][q] = 0.0f; }

    const int kt = H_DIM / 64;  // 32 chunks

    // prologue: issue chunk 0 into stage 0
    {
        uint32_t ab = sbase;
#pragma unroll
        for (int i = 0; i < 4; i++) cp16(ab + da[i], a_src[i]);
#pragma unroll
        for (int i = 0; i < 4; i++) cp16(ab + db[i], b1_src[i]);
#pragma unroll
        for (int i = 0; i < 4; i++) cp16(ab + db[i] + B13_W * 4, b3_src[i]);
        CP_COMMIT();
    }

    // ldmatrix mapping (R9-verified): row = lane&15, k-half(8) = lane>>4
    const int arow = wm * 32 + (lane & 15);
    const int akoff = (lane >> 4) * 8;   // halves

    for (int it = 0; it < kt; it++) {
        CP_WAIT0();        // chunk it complete (own writes)
        __syncthreads();   // publish chunk it; stage (it+1)&1 WAR-safe

        if (it + 1 < kt) {
            uint32_t ab = sbase + (uint32_t)((it + 1) & 1) * (STG13_W * 4);
            size_t k0 = (size_t)(it + 1) * 64;
            size_t kr = k0 * F_DIM;
#pragma unroll
            for (int i = 0; i < 4; i++) cp16(ab + da[i], a_src[i] + k0);
#pragma unroll
            for (int i = 0; i < 4; i++) cp16(ab + db[i], b1_src[i] + kr);
#pragma unroll
            for (int i = 0; i < 4; i++) cp16(ab + db[i] + B13_W * 4, b3_src[i] + kr);
            CP_COMMIT();
        }

        const uint32_t abase = sbase + (uint32_t)(it & 1) * (STG13_W * 4);
        const float* Bs1 = (const float*)(smem + (it & 1) * STG13_W + AS_W);
        const float* Bs3 = Bs1 + B13_W;

#pragma unroll
        for (int ks = 0; ks < 4; ks++) {
            uint32_t a[2][4];
#pragma unroll
            for (int mi = 0; mi < 2; mi++) {
                uint32_t ad = abase
                    + (uint32_t)((arow + mi * 16) * 72 + ks * 16 + akoff) * 2;
                ldsm4(a[mi][0], a[mi][1], a[mi][2], a[mi][3], ad);
            }
            const int rb = ks * 16 + 2 * tg;
#pragma unroll
            for (int ni = 0; ni < 4; ni++) {
                const int col = wn * 32 + ni * 8 + g;
                uint32_t b10 = pack_h2(Bs1[rb * BP13 + col], Bs1[(rb + 1) * BP13 + col]);
                uint32_t b11 = pack_h2(Bs1[(rb + 8) * BP13 + col], Bs1[(rb + 9) * BP13 + col]);
                uint32_t b30 = pack_h2(Bs3[rb * BP13 + col], Bs3[(rb + 1) * BP13 + col]);
                uint32_t b31 = pack_h2(Bs3[(rb + 8) * BP13 + col], Bs3[(rb + 9) * BP13 + col]);
#pragma unroll
                for (int mi = 0; mi < 2; mi++) {
                    mma_f16(c1[mi][ni][0], c1[mi][ni][1], c1[mi][ni][2], c1[mi][ni][3],
                            a[mi][0], a[mi][1], a[mi][2], a[mi][3], b10, b11);
                    mma_f16(c3[mi][ni][0], c3[mi][ni][1], c3[mi][ni][2], c3[mi][ni][3],
                            a[mi][0], a[mi][1], a[mi][2], a[mi][3], b30, b31);
                }
            }
        }
    }

    // epilogue (R8-verified, 4M x 2N)
    const int r_base = bm + wm * 32;
    const int c_base = bn + wn * 32;
#pragma unroll
    for (int mi = 0; mi < 2; mi++) {
        int r0 = r_base + mi * 16 + g;
        float wa = g_rw[r0];
        float wb = g_rw[r0 + 8];
        size_t o0 = (size_t)r0 * F_DIM;
        size_t o1 = (size_t)(r0 + 8) * F_DIM;
#pragma unroll
        for (int ni = 0; ni < 4; ni++) {
            int cl = c_base + ni * 8 + 2 * tg;
            __half2 v0 = __floats2half2_rn(silu_f(c1[mi][ni][0]) * c3[mi][ni][0] * wa,
                                           silu_f(c1[mi][ni][1]) * c3[mi][ni][1] * wa);
            __half2 v1 = __floats2half2_rn(silu_f(c1[mi][ni][2]) * c3[mi][ni][2] * wb,
                                           silu_f(c1[mi][ni][3]) * c3[mi][ni][3] * wb);
            *reinterpret_cast<__half2*>(g_A + o0 + cl) = v0;
            *reinterpret_cast<__half2*>(g_A + o1 + cl) = v1;
        }
    }
}

// ---------------------------------------------------------------------------
// GEMM2 (fp16 mma): g_Y[z] = g_A(:, z-quarter) @ w2[e](z-quarter, :).
// Block 128x128xK64, K-split 4, 2-stage pipeline, 1 barrier per chunk.
// ---------------------------------------------------------------------------
__global__ __launch_bounds__(256, 2) void gemm2_kernel(const float* __restrict__ w2) {
    extern __shared__ uint32_t smem[];

    const int my = blockIdx.y;
    const int e = g_tile_e[my];
    if (e < 0) return;
    const int z = blockIdx.z;

    const int tid = threadIdx.x;
    const int warp = tid >> 5;
    const int lane = tid & 31;
    const int wm = warp & 3;
    const int wn = warp >> 2;
    const int g = lane >> 2;
    const int tg = lane & 3;

    const int bm = my * 128;
    const int bn = blockIdx.x * 128;
    const int kseg = F_DIM / KSPLIT;   // 1024

    const __half* Abase = g_A + (size_t)z * kseg;
    const float* Bbase = w2 + (size_t)e * F_DIM * H_DIM + (size_t)z * kseg * H_DIM;
    const uint32_t sbase = smem_u32(smem);

    const __half* a_src[4];
    uint32_t da[4];
#pragma unroll
    for (int i = 0; i < 4; i++) {
        int slot = tid + i * 256;
        int r = slot >> 3;
        int q = slot & 7;
        a_src[i] = Abase + (size_t)(bm + r) * F_DIM + q * 8;
        da[i] = (uint32_t)(r * AP_W * 4 + q * 16);
    }
    // B staging: 2048 slots (64 rows x 32 quads), 8 per thread
    const float* b_src[8];
    uint32_t db[8];
#pragma unroll
    for (int i = 0; i < 8; i++) {
        int slot = tid + i * 256;
        int r = slot >> 5;
        int c4 = (slot & 31) << 2;
        b_src[i] = Bbase + (size_t)r * H_DIM + bn + c4;
        db[i] = (uint32_t)(AS_W + r * BP2 + c4) * 4u;
    }

    float c[2][8][4];
#pragma unroll
    for (int mi = 0; mi < 2; mi++)
#pragma unroll
        for (int ni = 0; ni < 8; ni++)
#pragma unroll
            for (int q = 0; q < 4; q++) c[mi][ni][q] = 0.0f;

    const int kt = kseg / 64;   // 16 chunks

    {
        uint32_t ab = sbase;
#pragma unroll
        for (int i = 0; i < 4; i++) cp16(ab + da[i], a_src[i]);
#pragma unroll
        for (int i = 0; i < 8; i++) cp16(ab + db[i], b_src[i]);
        CP_COMMIT();
    }

    const int arow = wm * 32 + (lane & 15);
    const int akoff = (lane >> 4) * 8;

    for (int it = 0; it < kt; it++) {
        CP_WAIT0();
        __syncthreads();

        if (it + 1 < kt) {
            uint32_t ab = sbase + (uint32_t)((it + 1) & 1) * (STG2_W * 4);
            size_t k0 = (size_t)(it + 1) * 64;
            size_t kr = k0 * H_DIM;
#pragma unroll
            for (int i = 0; i < 4; i++) cp16(ab + da[i], a_src[i] + k0);
#pragma unroll
            for (int i = 0; i < 8; i++) cp16(ab + db[i], b_src[i] + kr);
            CP_COMMIT();
        }

        const uint32_t abase = sbase + (uint32_t)(it & 1) * (STG2_W * 4);
        const float* Bsb = (const float*)(smem + (it & 1) * STG2_W + AS_W);

#pragma unroll
        for (int ks = 0; ks < 4; ks++) {
            uint32_t a[2][4];
#pragma unroll
            for (int mi = 0; mi < 2; mi++) {
                uint32_t ad = abase
                    + (uint32_t)((arow + mi * 16) * 72 + ks * 16 + akoff) * 2;
                ldsm4(a[mi][0], a[mi][1], a[mi][2], a[mi][3], ad);
            }
            const int rb = ks * 16 + 2 * tg;
#pragma unroll
            for (int ni = 0; ni < 8; ni++) {
                const int col = wn * 64 + ni * 8 + g;
                uint32_t b0 = pack_h2(Bsb[rb * BP2 + col], Bsb[(rb + 1) * BP2 + col]);
                uint32_t b1 = pack_h2(Bsb[(rb + 8) * BP2 + col], Bsb[(rb + 9) * BP2 + col]);
#pragma unroll
                for (int mi = 0; mi < 2; mi++)
                    mma_f16(c[mi][ni][0], c[mi][ni][1], c[mi][ni][2], c[mi][ni][3],
                            a[mi][0], a[mi][1], a[mi][2], a[mi][3], b0, b1);
            }
        }
    }

    float* Yp = g_Y + (size_t)z * ((size_t)ROWS_CAP * H_DIM);
    const int r_base = bm + wm * 32;
    const int c_base = bn + wn * 64;
#pragma unroll
    for (int mi = 0; mi < 2; mi++) {
        int r0 = r_base + mi * 16 + g;
        size_t o0 = (size_t)r0 * H_DIM;
        size_t o1 = (size_t)(r0 + 8) * H_DIM;
#pragma unroll
        for (int ni = 0; ni < 8; ni++) {
            int cl = c_base + ni * 8 + 2 * tg;
            *reinterpret_cast<float2*>(Yp + o0 + cl) = make_float2(c[mi][ni][0], c[mi][ni][1]);
            *reinterpret_cast<float2*>(Yp + o1 + cl) = make_float2(c[mi][ni][2], c[mi][ni][3]);
        }
    }
}

// out[t] = sum over (slot, kslice) — fixed order, deterministic
__global__ void combine_kernel(float* __restrict__ out) {
    int i = blockIdx.x * blockDim.x + threadIdx.x;
    int t = i >> 9;
    int h = (i & 511) << 2;
    size_t r0 = (size_t)g_pos[2 * t] * H_DIM + h;
    size_t r1 = (size_t)g_pos[2 * t + 1] * H_DIM + h;
    const size_t SL = (size_t)ROWS_CAP * H_DIM;
    float4 s0 = make_float4(0.f, 0.f, 0.f, 0.f);
    float4 s1 = make_float4(0.f, 0.f, 0.f, 0.f);
#pragma unroll
    for (int zz = 0; zz < KSPLIT; zz++) {
        float4 a = *reinterpret_cast<const float4*>(g_Y + zz * SL + r0);
        float4 b = *reinterpret_cast<const float4*>(g_Y + zz * SL + r1);
        s0.x += a.x; s0.y += a.y; s0.z += a.z; s0.w += a.w;
        s1.x += b.x; s1.y += b.y; s1.z += b.z; s1.w += b.w;
    }
    *reinterpret_cast<float4*>(out + (size_t)t * H_DIM + h) =
        make_float4(s0.x + s1.x, s0.y + s1.y, s0.z + s1.z, s0.w + s1.w);
}

extern "C" void kernel_launch(void* const* d_in, const int* in_sizes, int n_in,
                              void* d_out, int out_size) {
    const float* x  = (const float*)d_in[0];
    const float* wg = (const float*)d_in[1];
    const float* w1 = (const float*)d_in[2];
    const float* w3 = (const float*)d_in[3];
    const float* w2 = (const float*)d_in[4];
    float* out = (float*)d_out;

    cudaFuncSetAttribute(gemm13_kernel, cudaFuncAttributeMaxDynamicSharedMemorySize, SMEM13);
    cudaFuncSetAttribute(gemm2_kernel, cudaFuncAttributeMaxDynamicSharedMemorySize, SMEM2);

    gate_kernel<<<T_TOK / 8, 256>>>(x, wg);
    route_scatter_kernel<<<1, 256>>>();
    gather_kernel<<<ROWS_CAP * 512 / 256, 256>>>(x);

    dim3 g1(F_DIM / 64, MTILES);
    gemm13_kernel<<<g1, 256, SMEM13>>>(w1, w3);

    dim3 g2(H_DIM / 128, MTILES, KSPLIT);
    gemm2_kernel<<<g2, 256, SMEM2>>>(w2);

    combine_kernel<<<(T_TOK * H_DIM / 4) / 256, 256>>>(out);
}

// round 14
// speedup vs baseline: 1.5953x; 1.2113x over previous
#include <cuda_runtime.h>
#include <cuda.h>
#include <cuda_fp16.h>
#include <stdint.h>
#include <math.h>

#define T_TOK 1024
#define H_DIM 2048
#define F_DIM 4096
#define E_EXP 8
#define ROWS_CAP 3072
#define MTILES (ROWS_CAP / 128)   // 24
#define KSPLIT 4

// ---- gemm13 (TMA): stage = A(16KB fp16 SW128) + B1(16KB) + B3(16KB) ----
#define STG13_B 49152u
#define SMEM13 (1024 + 64 + 2 * 49152)   // slack for 1024-align + bars
// ---- gemm2 (cp.async, R13 verbatim) ----
#define AP_W 36
#define AS_W (128 * AP_W)         // 4608 words
#define BP2 132
#define B2_W (64 * BP2)           // 8448 words
#define STG2_W (AS_W + B2_W)      // 13056 words
#define SMEM2 (2 * STG2_W * 4)    // 104448 B

// ---------------- scratch ----------------
__device__ __align__(256) __half g_X[(size_t)ROWS_CAP * H_DIM];
__device__ __align__(256) __half g_A[(size_t)ROWS_CAP * F_DIM];
__device__ __align__(256) float  g_Y[(size_t)KSPLIT * ROWS_CAP * H_DIM];
__device__ int   g_off[E_EXP + 1];
__device__ int   g_tile_e[MTILES];
__device__ int   g_rows[ROWS_CAP];
__device__ float g_rw[ROWS_CAP];
__device__ int   g_pos[T_TOK * 2];
__device__ int   g_te[T_TOK * 2];
__device__ float g_tw[T_TOK * 2];

__device__ __forceinline__ float silu_f(float v) { return v / (1.0f + expf(-v)); }

__device__ __forceinline__ uint32_t smem_u32(const void* p) {
    uint32_t a;
    asm("{ .reg .u64 t; cvta.to.shared.u64 t, %1; cvt.u32.u64 %0, t; }" : "=r"(a) : "l"(p));
    return a;
}
__device__ __forceinline__ void cp16(uint32_t dst, const void* src) {
    asm volatile("cp.async.cg.shared.global [%0], [%1], 16;" :: "r"(dst), "l"(src));
}
#define CP_COMMIT() asm volatile("cp.async.commit_group;" ::: "memory")
#define CP_WAIT0()  asm volatile("cp.async.wait_group 0;" ::: "memory")

#define MBARRIER_INIT(a, c) \
    asm volatile("mbarrier.init.shared.b64 [%0], %1;" :: "r"((uint32_t)(a)), "r"((uint32_t)(c)) : "memory")
#define MBARRIER_EXPECT_TX(a, b) \
    asm volatile("mbarrier.arrive.expect_tx.shared.b64 _, [%0], %1;" :: "r"((uint32_t)(a)), "r"((uint32_t)(b)) : "memory")
#define MBAR_WAIT(a, ph) do { \
    uint32_t _m = (uint32_t)(a), _p = (uint32_t)(ph), _d; \
    asm volatile("{ .reg .pred p; mbarrier.try_wait.parity.acquire.cta.shared::cta.b64 p, [%1], %2; selp.b32 %0, 1, 0, p; }" \
        : "=r"(_d) : "r"(_m), "r"(_p) : "memory"); \
    if (!_d) asm volatile("{ .reg .pred P1; WL_%=: mbarrier.try_wait.parity.acquire.cta.shared::cta.b64 P1, [%0], %1, 0x989680; @P1 bra.uni WD_%=; bra.uni WL_%=; WD_%=: }" \
        :: "r"(_m), "r"(_p) : "memory"); } while (0)

#define TMA2D(sm, mp, c0, c1, mb) \
    asm volatile("cp.async.bulk.tensor.2d.shared::cta.global.tile.mbarrier::complete_tx::bytes [%0], [%1, {%2, %3}], [%4];" \
        :: "r"((uint32_t)(sm)), "l"(mp), "r"((int)(c0)), "r"((int)(c1)), "r"((uint32_t)(mb)) : "memory")
#define TMA3D(sm, mp, c0, c1, c2, mb) \
    asm volatile("cp.async.bulk.tensor.3d.shared::cta.global.tile.mbarrier::complete_tx::bytes [%0], [%1, {%2, %3, %4}], [%5];" \
        :: "r"((uint32_t)(sm)), "l"(mp), "r"((int)(c0)), "r"((int)(c1)), "r"((int)(c2)), "r"((uint32_t)(mb)) : "memory")

__device__ __forceinline__ float lds_f32(uint32_t a) {
    float v;
    asm volatile("ld.shared.f32 %0, [%1];" : "=f"(v) : "r"(a));
    return v;
}
__device__ __forceinline__ uint32_t pack_h2(float lo, float hi) {
    uint32_t d;
    asm("cvt.rn.f16x2.f32 %0, %1, %2;" : "=r"(d) : "f"(hi), "f"(lo));
    return d;
}
__device__ __forceinline__ void ldsm4(uint32_t& r0, uint32_t& r1, uint32_t& r2, uint32_t& r3,
                                      uint32_t addr) {
    asm volatile("ldmatrix.sync.aligned.m8n8.x4.shared.b16 {%0,%1,%2,%3}, [%4];"
        : "=r"(r0), "=r"(r1), "=r"(r2), "=r"(r3) : "r"(addr));
}
__device__ __forceinline__ void mma_f16(float& c0, float& c1, float& c2, float& c3,
                                        uint32_t a0, uint32_t a1, uint32_t a2, uint32_t a3,
                                        uint32_t b0, uint32_t b1) {
    asm volatile(
        "mma.sync.aligned.m16n8k16.row.col.f32.f16.f16.f32 "
        "{%0,%1,%2,%3}, {%4,%5,%6,%7}, {%8,%9}, {%0,%1,%2,%3};\n"
        : "+f"(c0), "+f"(c1), "+f"(c2), "+f"(c3)
        : "r"(a0), "r"(a1), "r"(a2), "r"(a3), "r"(b0), "r"(b1));
}

// ------------------------------- routing -----------------------------------
__global__ void gate_kernel(const float* __restrict__ x, const float* __restrict__ wg) {
    int t = blockIdx.x * (blockDim.x >> 5) + (threadIdx.x >> 5);
    int lane = threadIdx.x & 31;
    if (t >= T_TOK) return;
    const float* xr = x + (size_t)t * H_DIM;
    float acc[E_EXP];
#pragma unroll
    for (int e = 0; e < E_EXP; e++) acc[e] = 0.0f;
    for (int h = lane; h < H_DIM; h += 32) {
        float xv = xr[h];
        const float* wr = wg + (size_t)h * E_EXP;
#pragma unroll
        for (int e = 0; e < E_EXP; e++) acc[e] += xv * wr[e];
    }
#pragma unroll
    for (int e = 0; e < E_EXP; e++)
#pragma unroll
        for (int o = 16; o > 0; o >>= 1) acc[e] += __shfl_xor_sync(0xffffffffu, acc[e], o);
    if (lane == 0) {
        int i0 = 0; float v0 = acc[0];
#pragma unroll
        for (int e = 1; e < E_EXP; e++) if (acc[e] > v0) { v0 = acc[e]; i0 = e; }
        int i1 = -1; float v1 = -INFINITY;
#pragma unroll
        for (int e = 0; e < E_EXP; e++) if (e != i0 && acc[e] > v1) { v1 = acc[e]; i1 = e; }
        float w0 = 1.0f / (1.0f + expf(v1 - v0));
        g_te[2 * t] = i0;     g_tw[2 * t] = w0;
        g_te[2 * t + 1] = i1; g_tw[2 * t + 1] = 1.0f - w0;
    }
}

__global__ void route_scatter_kernel() {
    __shared__ int scnt[E_EXP], soff[E_EXP + 1], sfill[E_EXP];
    int tid = threadIdx.x;
    if (tid < E_EXP) { scnt[tid] = 0; sfill[tid] = 0; }
    __syncthreads();
    for (int i = tid; i < 2 * T_TOK; i += 256) atomicAdd(&scnt[g_te[i]], 1);
    __syncthreads();
    if (tid == 0) {
        int o = 0;
#pragma unroll
        for (int e = 0; e < E_EXP; e++) { soff[e] = o; o += (scnt[e] + 127) & ~127; }
        soff[E_EXP] = o;
#pragma unroll
        for (int e = 0; e <= E_EXP; e++) g_off[e] = soff[e];
    }
    __syncthreads();
    if (tid < MTILES) {
        int e = -1;
#pragma unroll
        for (int ee = 0; ee < E_EXP; ee++)
            if (tid * 128 >= soff[ee] && tid * 128 < soff[ee + 1]) e = ee;
        g_tile_e[tid] = e;
    }
    for (int r = tid; r < ROWS_CAP; r += 256) {
        g_rows[r] = 0;
        g_rw[r] = 0.0f;
    }
    __syncthreads();
    for (int t = tid; t < T_TOK; t += 256) {
#pragma unroll
        for (int s = 0; s < 2; s++) {
            int e = g_te[2 * t + s];
            int r = soff[e] + atomicAdd(&sfill[e], 1);
            g_rows[r] = t;
            g_rw[r] = g_tw[2 * t + s];
            g_pos[2 * t + s] = r;
        }
    }
}

__global__ void gather_kernel(const float* __restrict__ x) {
    int idx = blockIdx.x * blockDim.x + threadIdx.x;
    int r = idx >> 9;
    if (r >= g_off[E_EXP]) return;
    int h = (idx & 511) << 2;
    float4 v = *reinterpret_cast<const float4*>(x + (size_t)g_rows[r] * H_DIM + h);
    *reinterpret_cast<__half2*>(g_X + (size_t)r * H_DIM + h) = __floats2half2_rn(v.x, v.y);
    *reinterpret_cast<__half2*>(g_X + (size_t)r * H_DIM + h + 2) = __floats2half2_rn(v.z, v.w);
}

// ---------------------------------------------------------------------------
// GEMM1 fused, TMA edition. Block 128x64xK64, 8 warps (4M x 2N).
// Stage: A fp16 SW128 (rowpitch 128B) + B1/B3 f32 SW128 (2 panels of 32 cols).
// Swizzle: byte ^= ((byte>>3)&0x70)  (bits[6:4] ^= row&7) -> lane-const XORs.
// ---------------------------------------------------------------------------
__global__ __launch_bounds__(256, 2) void gemm13_kernel(
    const __grid_constant__ CUtensorMap tmA,
    const __grid_constant__ CUtensorMap tmB1,
    const __grid_constant__ CUtensorMap tmB3) {
    extern __shared__ uint32_t smem[];

    const int my = blockIdx.y;
    const int e = g_tile_e[my];
    if (e < 0) return;

    const int tid = threadIdx.x;
    const int warp = tid >> 5;
    const int lane = tid & 31;
    const int wm = warp & 3;
    const int wn = warp >> 2;
    const int g = lane >> 2;
    const int tg = lane & 3;

    const int bm = my * 128;
    const int bn = blockIdx.x * 64;

    const uint32_t sbase = smem_u32(smem);
    const uint32_t barb = sbase;                          // 2 mbarriers
    const uint32_t tiles = (sbase + 64 + 1023) & ~1023u;  // 1024-aligned

    if (tid == 0) {
        MBARRIER_INIT(barb, 1);
        MBARRIER_INIT(barb + 8, 1);
    }
    __syncthreads();

    // prologue: chunk 0 -> stage 0
    if (tid == 0) {
        MBARRIER_EXPECT_TX(barb, STG13_B);
        TMA2D(tiles, &tmA, 0, bm, barb);
        TMA3D(tiles + 16384, &tmB1, bn, 0, e, barb);
        TMA3D(tiles + 24576, &tmB1, bn + 32, 0, e, barb);
        TMA3D(tiles + 32768, &tmB3, bn, 0, e, barb);
        TMA3D(tiles + 40960, &tmB3, bn + 32, 0, e, barb);
    }

    float c1[2][4][4], c3[2][4][4];
#pragma unroll
    for (int mi = 0; mi < 2; mi++)
#pragma unroll
        for (int ni = 0; ni < 4; ni++)
#pragma unroll
            for (int q = 0; q < 4; q++) { c1[mi][ni][q] = 0.0f; c3[mi][ni][q] = 0.0f; }

    // lane-constant addressing
    const int arow = wm * 32 + (lane & 15);
    const uint32_t alow = (uint32_t)((lane >> 4) * 16);   // byte offset within A row
    uint32_t abasemi[2], axor[2];
#pragma unroll
    for (int mi = 0; mi < 2; mi++) {
        int r = arow + mi * 16;
        abasemi[mi] = (uint32_t)r << 7;
        axor[mi] = (uint32_t)(r & 7) << 4;
    }
    uint32_t bc0[4], bc1[4];
#pragma unroll
    for (int ni = 0; ni < 4; ni++) {
        uint32_t cb = (uint32_t)(ni * 8 + g) << 2;        // col byte within panel
        bc0[ni] = cb ^ ((uint32_t)(2 * tg) << 4);
        bc1[ni] = cb ^ ((uint32_t)(2 * tg + 1) << 4);
    }
    const uint32_t pb1 = tiles + 16384 + (uint32_t)wn * 8192;
    const uint32_t pb3 = tiles + 32768 + (uint32_t)wn * 8192;

    const int kt = H_DIM / 64;  // 32

    for (int it = 0; it < kt; it++) {
        MBAR_WAIT(barb + (it & 1) * 8, (it >> 1) & 1);
        __syncthreads();   // all warps past chunk it-1 compute -> stage (it+1)&1 WAR-safe

        if (tid == 0 && it + 1 < kt) {
            const uint32_t st = tiles + (uint32_t)((it + 1) & 1) * STG13_B;
            const uint32_t mb = barb + ((it + 1) & 1) * 8;
            const int k0 = (it + 1) * 64;
            MBARRIER_EXPECT_TX(mb, STG13_B);
            TMA2D(st, &tmA, k0, bm, mb);
            TMA3D(st + 16384, &tmB1, bn, k0, e, mb);
            TMA3D(st + 24576, &tmB1, bn + 32, k0, e, mb);
            TMA3D(st + 32768, &tmB3, bn, k0, e, mb);
            TMA3D(st + 40960, &tmB3, bn + 32, k0, e, mb);
        }

        const uint32_t soff = (uint32_t)(it & 1) * STG13_B;
        const uint32_t ab = tiles + soff;
#pragma unroll
        for (int ks = 0; ks < 4; ks++) {
            uint32_t a[2][4];
#pragma unroll
            for (int mi = 0; mi < 2; mi++) {
                uint32_t ad = ab + abasemi[mi]
                            + ((((uint32_t)ks << 5) | alow) ^ axor[mi]);
                ldsm4(a[mi][0], a[mi][1], a[mi][2], a[mi][3], ad);
            }
            const uint32_t rbyte = (uint32_t)(16 * ks + 2 * tg) << 7;
            const uint32_t r1b = pb1 + soff + rbyte;
            const uint32_t r3b = pb3 + soff + rbyte;
#pragma unroll
            for (int ni = 0; ni < 4; ni++) {
                float f0 = lds_f32(r1b + bc0[ni]);
                float f1 = lds_f32(r1b + 128 + bc1[ni]);
                float f2 = lds_f32(r1b + 1024 + bc0[ni]);
                float f3 = lds_f32(r1b + 1152 + bc1[ni]);
                uint32_t b10 = pack_h2(f0, f1);
                uint32_t b11 = pack_h2(f2, f3);
                float h0 = lds_f32(r3b + bc0[ni]);
                float h1 = lds_f32(r3b + 128 + bc1[ni]);
                float h2 = lds_f32(r3b + 1024 + bc0[ni]);
                float h3 = lds_f32(r3b + 1152 + bc1[ni]);
                uint32_t b30 = pack_h2(h0, h1);
                uint32_t b31 = pack_h2(h2, h3);
#pragma unroll
                for (int mi = 0; mi < 2; mi++) {
                    mma_f16(c1[mi][ni][0], c1[mi][ni][1], c1[mi][ni][2], c1[mi][ni][3],
                            a[mi][0], a[mi][1], a[mi][2], a[mi][3], b10, b11);
                    mma_f16(c3[mi][ni][0], c3[mi][ni][1], c3[mi][ni][2], c3[mi][ni][3],
                            a[mi][0], a[mi][1], a[mi][2], a[mi][3], b30, b31);
                }
            }
        }
    }

    // epilogue (R8-verified, 4M x 2N)
    const int r_base = bm + wm * 32;
    const int c_base = bn + wn * 32;
#pragma unroll
    for (int mi = 0; mi < 2; mi++) {
        int r0 = r_base + mi * 16 + g;
        float wa = g_rw[r0];
        float wb = g_rw[r0 + 8];
        size_t o0 = (size_t)r0 * F_DIM;
        size_t o1 = (size_t)(r0 + 8) * F_DIM;
#pragma unroll
        for (int ni = 0; ni < 4; ni++) {
            int cl = c_base + ni * 8 + 2 * tg;
            __half2 v0 = __floats2half2_rn(silu_f(c1[mi][ni][0]) * c3[mi][ni][0] * wa,
                                           silu_f(c1[mi][ni][1]) * c3[mi][ni][1] * wa);
            __half2 v1 = __floats2half2_rn(silu_f(c1[mi][ni][2]) * c3[mi][ni][2] * wb,
                                           silu_f(c1[mi][ni][3]) * c3[mi][ni][3] * wb);
            *reinterpret_cast<__half2*>(g_A + o0 + cl) = v0;
            *reinterpret_cast<__half2*>(g_A + o1 + cl) = v1;
        }
    }
}

// ---------------------------------------------------------------------------
// GEMM2 (R13 verbatim): block 128x128xK64, K-split 4, 2-stage cp.async.
// ---------------------------------------------------------------------------
__global__ __launch_bounds__(256, 2) void gemm2_kernel(const float* __restrict__ w2) {
    extern __shared__ uint32_t smem[];

    const int my = blockIdx.y;
    const int e = g_tile_e[my];
    if (e < 0) return;
    const int z = blockIdx.z;

    const int tid = threadIdx.x;
    const int warp = tid >> 5;
    const int lane = tid & 31;
    const int wm = warp & 3;
    const int wn = warp >> 2;
    const int g = lane >> 2;
    const int tg = lane & 3;

    const int bm = my * 128;
    const int bn = blockIdx.x * 128;
    const int kseg = F_DIM / KSPLIT;   // 1024

    const __half* Abase = g_A + (size_t)z * kseg;
    const float* Bbase = w2 + (size_t)e * F_DIM * H_DIM + (size_t)z * kseg * H_DIM;
    const uint32_t sbase = smem_u32(smem);

    const __half* a_src[4];
    uint32_t da[4];
#pragma unroll
    for (int i = 0; i < 4; i++) {
        int slot = tid + i * 256;
        int r = slot >> 3;
        int q = slot & 7;
        a_src[i] = Abase + (size_t)(bm + r) * F_DIM + q * 8;
        da[i] = (uint32_t)(r * AP_W * 4 + q * 16);
    }
    const float* b_src[8];
    uint32_t db[8];
#pragma unroll
    for (int i = 0; i < 8; i++) {
        int slot = tid + i * 256;
        int r = slot >> 5;
        int c4 = (slot & 31) << 2;
        b_src[i] = Bbase + (size_t)r * H_DIM + bn + c4;
        db[i] = (uint32_t)(AS_W + r * BP2 + c4) * 4u;
    }

    float c[2][8][4];
#pragma unroll
    for (int mi = 0; mi < 2; mi++)
#pragma unroll
        for (int ni = 0; ni < 8; ni++)
#pragma unroll
            for (int q = 0; q < 4; q++) c[mi][ni][q] = 0.0f;

    const int kt = kseg / 64;   // 16

    {
        uint32_t ab = sbase;
#pragma unroll
        for (int i = 0; i < 4; i++) cp16(ab + da[i], a_src[i]);
#pragma unroll
        for (int i = 0; i < 8; i++) cp16(ab + db[i], b_src[i]);
        CP_COMMIT();
    }

    const int arow = wm * 32 + (lane & 15);
    const int akoff = (lane >> 4) * 8;

    for (int it = 0; it < kt; it++) {
        CP_WAIT0();
        __syncthreads();

        if (it + 1 < kt) {
            uint32_t ab = sbase + (uint32_t)((it + 1) & 1) * (STG2_W * 4);
            size_t k0 = (size_t)(it + 1) * 64;
            size_t kr = k0 * H_DIM;
#pragma unroll
            for (int i = 0; i < 4; i++) cp16(ab + da[i], a_src[i] + k0);
#pragma unroll
            for (int i = 0; i < 8; i++) cp16(ab + db[i], b_src[i] + kr);
            CP_COMMIT();
        }

        const uint32_t abase = sbase + (uint32_t)(it & 1) * (STG2_W * 4);
        const float* Bsb = (const float*)(smem + (it & 1) * STG2_W + AS_W);

#pragma unroll
        for (int ks = 0; ks < 4; ks++) {
            uint32_t a[2][4];
#pragma unroll
            for (int mi = 0; mi < 2; mi++) {
                uint32_t ad = abase
                    + (uint32_t)((arow + mi * 16) * 72 + ks * 16 + akoff) * 2;
                ldsm4(a[mi][0], a[mi][1], a[mi][2], a[mi][3], ad);
            }
            const int rb = ks * 16 + 2 * tg;
#pragma unroll
            for (int ni = 0; ni < 8; ni++) {
                const int col = wn * 64 + ni * 8 + g;
                uint32_t b0 = pack_h2(Bsb[rb * BP2 + col], Bsb[(rb + 1) * BP2 + col]);
                uint32_t b1 = pack_h2(Bsb[(rb + 8) * BP2 + col], Bsb[(rb + 9) * BP2 + col]);
#pragma unroll
                for (int mi = 0; mi < 2; mi++)
                    mma_f16(c[mi][ni][0], c[mi][ni][1], c[mi][ni][2], c[mi][ni][3],
                            a[mi][0], a[mi][1], a[mi][2], a[mi][3], b0, b1);
            }
        }
    }

    float* Yp = g_Y + (size_t)z * ((size_t)ROWS_CAP * H_DIM);
    const int r_base = bm + wm * 32;
    const int c_base = bn + wn * 64;
#pragma unroll
    for (int mi = 0; mi < 2; mi++) {
        int r0 = r_base + mi * 16 + g;
        size_t o0 = (size_t)r0 * H_DIM;
        size_t o1 = (size_t)(r0 + 8) * H_DIM;
#pragma unroll
        for (int ni = 0; ni < 8; ni++) {
            int cl = c_base + ni * 8 + 2 * tg;
            *reinterpret_cast<float2*>(Yp + o0 + cl) = make_float2(c[mi][ni][0], c[mi][ni][1]);
            *reinterpret_cast<float2*>(Yp + o1 + cl) = make_float2(c[mi][ni][2], c[mi][ni][3]);
        }
    }
}

__global__ void combine_kernel(float* __restrict__ out) {
    int i = blockIdx.x * blockDim.x + threadIdx.x;
    int t = i >> 9;
    int h = (i & 511) << 2;
    size_t r0 = (size_t)g_pos[2 * t] * H_DIM + h;
    size_t r1 = (size_t)g_pos[2 * t + 1] * H_DIM + h;
    const size_t SL = (size_t)ROWS_CAP * H_DIM;
    float4 s0 = make_float4(0.f, 0.f, 0.f, 0.f);
    float4 s1 = make_float4(0.f, 0.f, 0.f, 0.f);
#pragma unroll
    for (int zz = 0; zz < KSPLIT; zz++) {
        float4 a = *reinterpret_cast<const float4*>(g_Y + zz * SL + r0);
        float4 b = *reinterpret_cast<const float4*>(g_Y + zz * SL + r1);
        s0.x += a.x; s0.y += a.y; s0.z += a.z; s0.w += a.w;
        s1.x += b.x; s1.y += b.y; s1.z += b.z; s1.w += b.w;
    }
    *reinterpret_cast<float4*>(out + (size_t)t * H_DIM + h) =
        make_float4(s0.x + s1.x, s0.y + s1.y, s0.z + s1.z, s0.w + s1.w);
}

// ------------------------------- host --------------------------------------
typedef CUresult (*encode_fn_t)(CUtensorMap*, CUtensorMapDataType, unsigned, void*,
                                const unsigned long long*, const unsigned long long*,
                                const unsigned*, const unsigned*, CUtensorMapInterleave,
                                CUtensorMapSwizzle, CUtensorMapL2promotion,
                                CUtensorMapFloatOOBfill);

extern "C" void kernel_launch(void* const* d_in, const int* in_sizes, int n_in,
                              void* d_out, int out_size) {
    const float* x  = (const float*)d_in[0];
    const float* wg = (const float*)d_in[1];
    const float* w1 = (const float*)d_in[2];
    const float* w3 = (const float*)d_in[3];
    const float* w2 = (const float*)d_in[4];
    float* out = (float*)d_out;

    void* encp = nullptr;
    cudaDriverEntryPointQueryResult qr;
    cudaGetDriverEntryPoint("cuTensorMapEncodeTiled", &encp, cudaEnableDefault, &qr);
    encode_fn_t enc = (encode_fn_t)encp;

    void* pX = nullptr; cudaGetSymbolAddress(&pX, g_X);

    // A: g_X fp16, dims (H, ROWS), box (64, 128), SW128
    CUtensorMap tmA;
    {
        unsigned long long dims[2] = {H_DIM, ROWS_CAP};
        unsigned long long strides[1] = {H_DIM * 2ull};
        unsigned box[2] = {64u, 128u};
        unsigned es[2] = {1u, 1u};
        enc(&tmA, CU_TENSOR_MAP_DATA_TYPE_FLOAT16, 2, pX, dims, strides, box, es,
            CU_TENSOR_MAP_INTERLEAVE_NONE, CU_TENSOR_MAP_SWIZZLE_128B,
            CU_TENSOR_MAP_L2_PROMOTION_L2_128B, CU_TENSOR_MAP_FLOAT_OOB_FILL_NONE);
    }
    // B: w1/w3 f32, dims (F, H, E), box (32, 64, 1), SW128
    CUtensorMap tmW1, tmW3;
    {
        unsigned long long dims[3] = {F_DIM, H_DIM, E_EXP};
        unsigned long long strides[2] = {F_DIM * 4ull, (unsigned long long)F_DIM * H_DIM * 4ull};
        unsigned box[3] = {32u, 64u, 1u};
        unsigned es[3] = {1u, 1u, 1u};
        enc(&tmW1, CU_TENSOR_MAP_DATA_TYPE_FLOAT32, 3, (void*)w1, dims, strides, box, es,
            CU_TENSOR_MAP_INTERLEAVE_NONE, CU_TENSOR_MAP_SWIZZLE_128B,
            CU_TENSOR_MAP_L2_PROMOTION_L2_128B, CU_TENSOR_MAP_FLOAT_OOB_FILL_NONE);
        enc(&tmW3, CU_TENSOR_MAP_DATA_TYPE_FLOAT32, 3, (void*)w3, dims, strides, box, es,
            CU_TENSOR_MAP_INTERLEAVE_NONE, CU_TENSOR_MAP_SWIZZLE_128B,
            CU_TENSOR_MAP_L2_PROMOTION_L2_128B, CU_TENSOR_MAP_FLOAT_OOB_FILL_NONE);
    }

    cudaFuncSetAttribute(gemm13_kernel, cudaFuncAttributeMaxDynamicSharedMemorySize, SMEM13);
    cudaFuncSetAttribute(gemm2_kernel, cudaFuncAttributeMaxDynamicSharedMemorySize, SMEM2);

    gate_kernel<<<T_TOK / 8, 256>>>(x, wg);
    route_scatter_kernel<<<1, 256>>>();
    gather_kernel<<<ROWS_CAP * 512 / 256, 256>>>(x);

    dim3 g1(F_DIM / 64, MTILES);
    gemm13_kernel<<<g1, 256, SMEM13>>>(tmA, tmW1, tmW3);

    dim3 g2(H_DIM / 128, MTILES, KSPLIT);
    gemm2_kernel<<<g2, 256, SMEM2>>>(w2);

    combine_kernel<<<(T_TOK * H_DIM / 4) / 256, 256>>>(out);
}

// round 15
// speedup vs baseline: 1.8527x; 1.1614x over previous
#include <cuda_runtime.h>
#include <cuda.h>
#include <cuda_fp16.h>
#include <stdint.h>
#include <math.h>

#define T_TOK 1024
#define H_DIM 2048
#define F_DIM 4096
#define E_EXP 8
#define ROWS_CAP 3072
#define MTILES (ROWS_CAP / 128)   // 24
#define KSPLIT 4

// stage = A(16KB fp16 SW128) + B panels (f32 SW128, 8KB each)
#define STG13_B 49152u            // A + 2x2 panels (w1,w3)
#define SMEM13 (1024 + 64 + 2 * 49152)
#define STG2_B 49152u             // A + 4 panels (w2)
#define SMEM2 (1024 + 64 + 2 * 49152)

// ---------------- scratch ----------------
__device__ __align__(256) __half g_X[(size_t)ROWS_CAP * H_DIM];
__device__ __align__(256) __half g_A[(size_t)ROWS_CAP * F_DIM];
__device__ __align__(256) float  g_Y[(size_t)KSPLIT * ROWS_CAP * H_DIM];
__device__ int   g_off[E_EXP + 1];
__device__ int   g_tile_e[MTILES];
__device__ int   g_rows[ROWS_CAP];
__device__ float g_rw[ROWS_CAP];
__device__ int   g_pos[T_TOK * 2];
__device__ int   g_te[T_TOK * 2];
__device__ float g_tw[T_TOK * 2];

__device__ __forceinline__ float silu_f(float v) { return v / (1.0f + expf(-v)); }

__device__ __forceinline__ uint32_t smem_u32(const void* p) {
    uint32_t a;
    asm("{ .reg .u64 t; cvta.to.shared.u64 t, %1; cvt.u32.u64 %0, t; }" : "=r"(a) : "l"(p));
    return a;
}

#define MBARRIER_INIT(a, c) \
    asm volatile("mbarrier.init.shared.b64 [%0], %1;" :: "r"((uint32_t)(a)), "r"((uint32_t)(c)) : "memory")
#define MBARRIER_EXPECT_TX(a, b) \
    asm volatile("mbarrier.arrive.expect_tx.shared.b64 _, [%0], %1;" :: "r"((uint32_t)(a)), "r"((uint32_t)(b)) : "memory")
#define MBAR_WAIT(a, ph) do { \
    uint32_t _m = (uint32_t)(a), _p = (uint32_t)(ph), _d; \
    asm volatile("{ .reg .pred p; mbarrier.try_wait.parity.acquire.cta.shared::cta.b64 p, [%1], %2; selp.b32 %0, 1, 0, p; }" \
        : "=r"(_d) : "r"(_m), "r"(_p) : "memory"); \
    if (!_d) asm volatile("{ .reg .pred P1; WL_%=: mbarrier.try_wait.parity.acquire.cta.shared::cta.b64 P1, [%0], %1, 0x989680; @P1 bra.uni WD_%=; bra.uni WL_%=; WD_%=: }" \
        :: "r"(_m), "r"(_p) : "memory"); } while (0)

#define TMA2D(sm, mp, c0, c1, mb) \
    asm volatile("cp.async.bulk.tensor.2d.shared::cta.global.tile.mbarrier::complete_tx::bytes [%0], [%1, {%2, %3}], [%4];" \
        :: "r"((uint32_t)(sm)), "l"(mp), "r"((int)(c0)), "r"((int)(c1)), "r"((uint32_t)(mb)) : "memory")
#define TMA3D(sm, mp, c0, c1, c2, mb) \
    asm volatile("cp.async.bulk.tensor.3d.shared::cta.global.tile.mbarrier::complete_tx::bytes [%0], [%1, {%2, %3, %4}], [%5];" \
        :: "r"((uint32_t)(sm)), "l"(mp), "r"((int)(c0)), "r"((int)(c1)), "r"((int)(c2)), "r"((uint32_t)(mb)) : "memory")

__device__ __forceinline__ float lds_f32(uint32_t a) {
    float v;
    asm volatile("ld.shared.f32 %0, [%1];" : "=f"(v) : "r"(a));
    return v;
}
__device__ __forceinline__ uint32_t pack_h2(float lo, float hi) {
    uint32_t d;
    asm("cvt.rn.f16x2.f32 %0, %1, %2;" : "=r"(d) : "f"(hi), "f"(lo));
    return d;
}
__device__ __forceinline__ void ldsm4(uint32_t& r0, uint32_t& r1, uint32_t& r2, uint32_t& r3,
                                      uint32_t addr) {
    asm volatile("ldmatrix.sync.aligned.m8n8.x4.shared.b16 {%0,%1,%2,%3}, [%4];"
        : "=r"(r0), "=r"(r1), "=r"(r2), "=r"(r3) : "r"(addr));
}
__device__ __forceinline__ void mma_f16(float& c0, float& c1, float& c2, float& c3,
                                        uint32_t a0, uint32_t a1, uint32_t a2, uint32_t a3,
                                        uint32_t b0, uint32_t b1) {
    asm volatile(
        "mma.sync.aligned.m16n8k16.row.col.f32.f16.f16.f32 "
        "{%0,%1,%2,%3}, {%4,%5,%6,%7}, {%8,%9}, {%0,%1,%2,%3};\n"
        : "+f"(c0), "+f"(c1), "+f"(c2), "+f"(c3)
        : "r"(a0), "r"(a1), "r"(a2), "r"(a3), "r"(b0), "r"(b1));
}

// ------------------------------- routing -----------------------------------
__global__ void gate_kernel(const float* __restrict__ x, const float* __restrict__ wg) {
    int t = blockIdx.x * (blockDim.x >> 5) + (threadIdx.x >> 5);
    int lane = threadIdx.x & 31;
    if (t >= T_TOK) return;
    const float* xr = x + (size_t)t * H_DIM;
    float acc[E_EXP];
#pragma unroll
    for (int e = 0; e < E_EXP; e++) acc[e] = 0.0f;
    for (int h = lane; h < H_DIM; h += 32) {
        float xv = xr[h];
        const float* wr = wg + (size_t)h * E_EXP;
#pragma unroll
        for (int e = 0; e < E_EXP; e++) acc[e] += xv * wr[e];
    }
#pragma unroll
    for (int e = 0; e < E_EXP; e++)
#pragma unroll
        for (int o = 16; o > 0; o >>= 1) acc[e] += __shfl_xor_sync(0xffffffffu, acc[e], o);
    if (lane == 0) {
        int i0 = 0; float v0 = acc[0];
#pragma unroll
        for (int e = 1; e < E_EXP; e++) if (acc[e] > v0) { v0 = acc[e]; i0 = e; }
        int i1 = -1; float v1 = -INFINITY;
#pragma unroll
        for (int e = 0; e < E_EXP; e++) if (e != i0 && acc[e] > v1) { v1 = acc[e]; i1 = e; }
        float w0 = 1.0f / (1.0f + expf(v1 - v0));
        g_te[2 * t] = i0;     g_tw[2 * t] = w0;
        g_te[2 * t + 1] = i1; g_tw[2 * t + 1] = 1.0f - w0;
    }
}

__global__ void route_scatter_kernel() {
    __shared__ int scnt[E_EXP], soff[E_EXP + 1], sfill[E_EXP];
    int tid = threadIdx.x;
    if (tid < E_EXP) { scnt[tid] = 0; sfill[tid] = 0; }
    __syncthreads();
    for (int i = tid; i < 2 * T_TOK; i += 256) atomicAdd(&scnt[g_te[i]], 1);
    __syncthreads();
    if (tid == 0) {
        int o = 0;
#pragma unroll
        for (int e = 0; e < E_EXP; e++) { soff[e] = o; o += (scnt[e] + 127) & ~127; }
        soff[E_EXP] = o;
#pragma unroll
        for (int e = 0; e <= E_EXP; e++) g_off[e] = soff[e];
    }
    __syncthreads();
    if (tid < MTILES) {
        int e = -1;
#pragma unroll
        for (int ee = 0; ee < E_EXP; ee++)
            if (tid * 128 >= soff[ee] && tid * 128 < soff[ee + 1]) e = ee;
        g_tile_e[tid] = e;
    }
    for (int r = tid; r < ROWS_CAP; r += 256) {
        g_rows[r] = 0;
        g_rw[r] = 0.0f;
    }
    __syncthreads();
    for (int t = tid; t < T_TOK; t += 256) {
#pragma unroll
        for (int s = 0; s < 2; s++) {
            int e = g_te[2 * t + s];
            int r = soff[e] + atomicAdd(&sfill[e], 1);
            g_rows[r] = t;
            g_rw[r] = g_tw[2 * t + s];
            g_pos[2 * t + s] = r;
        }
    }
}

__global__ void gather_kernel(const float* __restrict__ x) {
    int idx = blockIdx.x * blockDim.x + threadIdx.x;
    int r = idx >> 9;
    if (r >= g_off[E_EXP]) return;
    int h = (idx & 511) << 2;
    float4 v = *reinterpret_cast<const float4*>(x + (size_t)g_rows[r] * H_DIM + h);
    *reinterpret_cast<__half2*>(g_X + (size_t)r * H_DIM + h) = __floats2half2_rn(v.x, v.y);
    *reinterpret_cast<__half2*>(g_X + (size_t)r * H_DIM + h + 2) = __floats2half2_rn(v.z, v.w);
}

// ---------------------------------------------------------------------------
// GEMM1 fused, TMA (R14 verbatim). Block 128x64xK64, 8 warps (4M x 2N).
// ---------------------------------------------------------------------------
__global__ __launch_bounds__(256, 2) void gemm13_kernel(
    const __grid_constant__ CUtensorMap tmA,
    const __grid_constant__ CUtensorMap tmB1,
    const __grid_constant__ CUtensorMap tmB3) {
    extern __shared__ uint32_t smem[];

    const int my = blockIdx.y;
    const int e = g_tile_e[my];
    if (e < 0) return;

    const int tid = threadIdx.x;
    const int warp = tid >> 5;
    const int lane = tid & 31;
    const int wm = warp & 3;
    const int wn = warp >> 2;
    const int g = lane >> 2;
    const int tg = lane & 3;

    const int bm = my * 128;
    const int bn = blockIdx.x * 64;

    const uint32_t sbase = smem_u32(smem);
    const uint32_t barb = sbase;
    const uint32_t tiles = (sbase + 64 + 1023) & ~1023u;

    if (tid == 0) {
        MBARRIER_INIT(barb, 1);
        MBARRIER_INIT(barb + 8, 1);
    }
    __syncthreads();

    if (tid == 0) {
        MBARRIER_EXPECT_TX(barb, STG13_B);
        TMA2D(tiles, &tmA, 0, bm, barb);
        TMA3D(tiles + 16384, &tmB1, bn, 0, e, barb);
        TMA3D(tiles + 24576, &tmB1, bn + 32, 0, e, barb);
        TMA3D(tiles + 32768, &tmB3, bn, 0, e, barb);
        TMA3D(tiles + 40960, &tmB3, bn + 32, 0, e, barb);
    }

    float c1[2][4][4], c3[2][4][4];
#pragma unroll
    for (int mi = 0; mi < 2; mi++)
#pragma unroll
        for (int ni = 0; ni < 4; ni++)
#pragma unroll
            for (int q = 0; q < 4; q++) { c1[mi][ni][q] = 0.0f; c3[mi][ni][q] = 0.0f; }

    const int arow = wm * 32 + (lane & 15);
    const uint32_t alow = (uint32_t)((lane >> 4) * 16);
    uint32_t abasemi[2], axor[2];
#pragma unroll
    for (int mi = 0; mi < 2; mi++) {
        int r = arow + mi * 16;
        abasemi[mi] = (uint32_t)r << 7;
        axor[mi] = (uint32_t)(r & 7) << 4;
    }
    uint32_t bc0[4], bc1[4];
#pragma unroll
    for (int ni = 0; ni < 4; ni++) {
        uint32_t cb = (uint32_t)(ni * 8 + g) << 2;
        bc0[ni] = cb ^ ((uint32_t)(2 * tg) << 4);
        bc1[ni] = cb ^ ((uint32_t)(2 * tg + 1) << 4);
    }
    const uint32_t pb1 = tiles + 16384 + (uint32_t)wn * 8192;
    const uint32_t pb3 = tiles + 32768 + (uint32_t)wn * 8192;

    const int kt = H_DIM / 64;  // 32

    for (int it = 0; it < kt; it++) {
        MBAR_WAIT(barb + (it & 1) * 8, (it >> 1) & 1);
        __syncthreads();

        if (tid == 0 && it + 1 < kt) {
            const uint32_t st = tiles + (uint32_t)((it + 1) & 1) * STG13_B;
            const uint32_t mb = barb + ((it + 1) & 1) * 8;
            const int k0 = (it + 1) * 64;
            MBARRIER_EXPECT_TX(mb, STG13_B);
            TMA2D(st, &tmA, k0, bm, mb);
            TMA3D(st + 16384, &tmB1, bn, k0, e, mb);
            TMA3D(st + 24576, &tmB1, bn + 32, k0, e, mb);
            TMA3D(st + 32768, &tmB3, bn, k0, e, mb);
            TMA3D(st + 40960, &tmB3, bn + 32, k0, e, mb);
        }

        const uint32_t soff = (uint32_t)(it & 1) * STG13_B;
        const uint32_t ab = tiles + soff;
#pragma unroll
        for (int ks = 0; ks < 4; ks++) {
            uint32_t a[2][4];
#pragma unroll
            for (int mi = 0; mi < 2; mi++) {
                uint32_t ad = ab + abasemi[mi]
                            + ((((uint32_t)ks << 5) | alow) ^ axor[mi]);
                ldsm4(a[mi][0], a[mi][1], a[mi][2], a[mi][3], ad);
            }
            const uint32_t rbyte = (uint32_t)(16 * ks + 2 * tg) << 7;
            const uint32_t r1b = pb1 + soff + rbyte;
            const uint32_t r3b = pb3 + soff + rbyte;
#pragma unroll
            for (int ni = 0; ni < 4; ni++) {
                float f0 = lds_f32(r1b + bc0[ni]);
                float f1 = lds_f32(r1b + 128 + bc1[ni]);
                float f2 = lds_f32(r1b + 1024 + bc0[ni]);
                float f3 = lds_f32(r1b + 1152 + bc1[ni]);
                uint32_t b10 = pack_h2(f0, f1);
                uint32_t b11 = pack_h2(f2, f3);
                float h0 = lds_f32(r3b + bc0[ni]);
                float h1 = lds_f32(r3b + 128 + bc1[ni]);
                float h2 = lds_f32(r3b + 1024 + bc0[ni]);
                float h3 = lds_f32(r3b + 1152 + bc1[ni]);
                uint32_t b30 = pack_h2(h0, h1);
                uint32_t b31 = pack_h2(h2, h3);
#pragma unroll
                for (int mi = 0; mi < 2; mi++) {
                    mma_f16(c1[mi][ni][0], c1[mi][ni][1], c1[mi][ni][2], c1[mi][ni][3],
                            a[mi][0], a[mi][1], a[mi][2], a[mi][3], b10, b11);
                    mma_f16(c3[mi][ni][0], c3[mi][ni][1], c3[mi][ni][2], c3[mi][ni][3],
                            a[mi][0], a[mi][1], a[mi][2], a[mi][3], b30, b31);
                }
            }
        }
    }

    const int r_base = bm + wm * 32;
    const int c_base = bn + wn * 32;
#pragma unroll
    for (int mi = 0; mi < 2; mi++) {
        int r0 = r_base + mi * 16 + g;
        float wa = g_rw[r0];
        float wb = g_rw[r0 + 8];
        size_t o0 = (size_t)r0 * F_DIM;
        size_t o1 = (size_t)(r0 + 8) * F_DIM;
#pragma unroll
        for (int ni = 0; ni < 4; ni++) {
            int cl = c_base + ni * 8 + 2 * tg;
            __half2 v0 = __floats2half2_rn(silu_f(c1[mi][ni][0]) * c3[mi][ni][0] * wa,
                                           silu_f(c1[mi][ni][1]) * c3[mi][ni][1] * wa);
            __half2 v1 = __floats2half2_rn(silu_f(c1[mi][ni][2]) * c3[mi][ni][2] * wb,
                                           silu_f(c1[mi][ni][3]) * c3[mi][ni][3] * wb);
            *reinterpret_cast<__half2*>(g_A + o0 + cl) = v0;
            *reinterpret_cast<__half2*>(g_A + o1 + cl) = v1;
        }
    }
}

// ---------------------------------------------------------------------------
// GEMM2, TMA edition. Block 128x128xK64, K-split 4, 8 warps (4M x 2N).
// A = g_A fp16 SW128 (box 64x128); B = w2 f32 SW128, 4 panels of 32 cols.
// Warp tile N=64 = panels {2wn, 2wn+1}; ni>>2 selects panel, ni&3 the col oct.
// ---------------------------------------------------------------------------
__global__ __launch_bounds__(256, 2) void gemm2_kernel(
    const __grid_constant__ CUtensorMap tmA2,
    const __grid_constant__ CUtensorMap tmB2) {
    extern __shared__ uint32_t smem[];

    const int my = blockIdx.y;
    const int e = g_tile_e[my];
    if (e < 0) return;
    const int z = blockIdx.z;

    const int tid = threadIdx.x;
    const int warp = tid >> 5;
    const int lane = tid & 31;
    const int wm = warp & 3;
    const int wn = warp >> 2;
    const int g = lane >> 2;
    const int tg = lane & 3;

    const int bm = my * 128;
    const int bn = blockIdx.x * 128;
    const int kbase = z * (F_DIM / KSPLIT);   // K-slice origin

    const uint32_t sbase = smem_u32(smem);
    const uint32_t barb = sbase;
    const uint32_t tiles = (sbase + 64 + 1023) & ~1023u;

    if (tid == 0) {
        MBARRIER_INIT(barb, 1);
        MBARRIER_INIT(barb + 8, 1);
    }
    __syncthreads();

    if (tid == 0) {
        MBARRIER_EXPECT_TX(barb, STG2_B);
        TMA2D(tiles, &tmA2, kbase, bm, barb);
#pragma unroll
        for (int p = 0; p < 4; p++)
            TMA3D(tiles + 16384 + p * 8192, &tmB2, bn + p * 32, kbase, e, barb);
    }

    float c[2][8][4];
#pragma unroll
    for (int mi = 0; mi < 2; mi++)
#pragma unroll
        for (int ni = 0; ni < 8; ni++)
#pragma unroll
            for (int q = 0; q < 4; q++) c[mi][ni][q] = 0.0f;

    const int arow = wm * 32 + (lane & 15);
    const uint32_t alow = (uint32_t)((lane >> 4) * 16);
    uint32_t abasemi[2], axor[2];
#pragma unroll
    for (int mi = 0; mi < 2; mi++) {
        int r = arow + mi * 16;
        abasemi[mi] = (uint32_t)r << 7;
        axor[mi] = (uint32_t)(r & 7) << 4;
    }
    uint32_t bc0[4], bc1[4];
#pragma unroll
    for (int nj = 0; nj < 4; nj++) {
        uint32_t cb = (uint32_t)(nj * 8 + g) << 2;
        bc0[nj] = cb ^ ((uint32_t)(2 * tg) << 4);
        bc1[nj] = cb ^ ((uint32_t)(2 * tg + 1) << 4);
    }
    const uint32_t pb0 = tiles + 16384 + (uint32_t)(2 * wn) * 8192;      // panel 2wn
    const uint32_t pb1p = pb0 + 8192;                                    // panel 2wn+1

    const int kt = (F_DIM / KSPLIT) / 64;   // 16

    for (int it = 0; it < kt; it++) {
        MBAR_WAIT(barb + (it & 1) * 8, (it >> 1) & 1);
        __syncthreads();

        if (tid == 0 && it + 1 < kt) {
            const uint32_t st = tiles + (uint32_t)((it + 1) & 1) * STG2_B;
            const uint32_t mb = barb + ((it + 1) & 1) * 8;
            const int k0 = kbase + (it + 1) * 64;
            MBARRIER_EXPECT_TX(mb, STG2_B);
            TMA2D(st, &tmA2, k0, bm, mb);
#pragma unroll
            for (int p = 0; p < 4; p++)
                TMA3D(st + 16384 + p * 8192, &tmB2, bn + p * 32, k0, e, mb);
        }

        const uint32_t soff = (uint32_t)(it & 1) * STG2_B;
        const uint32_t ab = tiles + soff;
#pragma unroll
        for (int ks = 0; ks < 4; ks++) {
            uint32_t a[2][4];
#pragma unroll
            for (int mi = 0; mi < 2; mi++) {
                uint32_t ad = ab + abasemi[mi]
                            + ((((uint32_t)ks << 5) | alow) ^ axor[mi]);
                ldsm4(a[mi][0], a[mi][1], a[mi][2], a[mi][3], ad);
            }
            const uint32_t rbyte = (uint32_t)(16 * ks + 2 * tg) << 7;
            const uint32_t rp0 = pb0 + soff + rbyte;
            const uint32_t rp1 = pb1p + soff + rbyte;
#pragma unroll
            for (int ni = 0; ni < 8; ni++) {
                const uint32_t rp = (ni < 4) ? rp0 : rp1;
                const int nj = ni & 3;
                float f0 = lds_f32(rp + bc0[nj]);
                float f1 = lds_f32(rp + 128 + bc1[nj]);
                float f2 = lds_f32(rp + 1024 + bc0[nj]);
                float f3 = lds_f32(rp + 1152 + bc1[nj]);
                uint32_t b0 = pack_h2(f0, f1);
                uint32_t b1 = pack_h2(f2, f3);
#pragma unroll
                for (int mi = 0; mi < 2; mi++)
                    mma_f16(c[mi][ni][0], c[mi][ni][1], c[mi][ni][2], c[mi][ni][3],
                            a[mi][0], a[mi][1], a[mi][2], a[mi][3], b0, b1);
            }
        }
    }

    float* Yp = g_Y + (size_t)z * ((size_t)ROWS_CAP * H_DIM);
    const int r_base = bm + wm * 32;
    const int c_base = bn + wn * 64;
#pragma unroll
    for (int mi = 0; mi < 2; mi++) {
        int r0 = r_base + mi * 16 + g;
        size_t o0 = (size_t)r0 * H_DIM;
        size_t o1 = (size_t)(r0 + 8) * H_DIM;
#pragma unroll
        for (int ni = 0; ni < 8; ni++) {
            int cl = c_base + ni * 8 + 2 * tg;
            *reinterpret_cast<float2*>(Yp + o0 + cl) = make_float2(c[mi][ni][0], c[mi][ni][1]);
            *reinterpret_cast<float2*>(Yp + o1 + cl) = make_float2(c[mi][ni][2], c[mi][ni][3]);
        }
    }
}

__global__ void combine_kernel(float* __restrict__ out) {
    int i = blockIdx.x * blockDim.x + threadIdx.x;
    int t = i >> 9;
    int h = (i & 511) << 2;
    size_t r0 = (size_t)g_pos[2 * t] * H_DIM + h;
    size_t r1 = (size_t)g_pos[2 * t + 1] * H_DIM + h;
    const size_t SL = (size_t)ROWS_CAP * H_DIM;
    float4 s0 = make_float4(0.f, 0.f, 0.f, 0.f);
    float4 s1 = make_float4(0.f, 0.f, 0.f, 0.f);
#pragma unroll
    for (int zz = 0; zz < KSPLIT; zz++) {
        float4 a = *reinterpret_cast<const float4*>(g_Y + zz * SL + r0);
        float4 b = *reinterpret_cast<const float4*>(g_Y + zz * SL + r1);
        s0.x += a.x; s0.y += a.y; s0.z += a.z; s0.w += a.w;
        s1.x += b.x; s1.y += b.y; s1.z += b.z; s1.w += b.w;
    }
    *reinterpret_cast<float4*>(out + (size_t)t * H_DIM + h) =
        make_float4(s0.x + s1.x, s0.y + s1.y, s0.z + s1.z, s0.w + s1.w);
}

// ------------------------------- host --------------------------------------
typedef CUresult (*encode_fn_t)(CUtensorMap*, CUtensorMapDataType, unsigned, void*,
                                const unsigned long long*, const unsigned long long*,
                                const unsigned*, const unsigned*, CUtensorMapInterleave,
                                CUtensorMapSwizzle, CUtensorMapL2promotion,
                                CUtensorMapFloatOOBfill);

extern "C" void kernel_launch(void* const* d_in, const int* in_sizes, int n_in,
                              void* d_out, int out_size) {
    const float* x  = (const float*)d_in[0];
    const float* wg = (const float*)d_in[1];
    const float* w1 = (const float*)d_in[2];
    const float* w3 = (const float*)d_in[3];
    const float* w2 = (const float*)d_in[4];
    float* out = (float*)d_out;

    void* encp = nullptr;
    cudaDriverEntryPointQueryResult qr;
    cudaGetDriverEntryPoint("cuTensorMapEncodeTiled", &encp, cudaEnableDefault, &qr);
    encode_fn_t enc = (encode_fn_t)encp;

    void* pX = nullptr; cudaGetSymbolAddress(&pX, g_X);
    void* pA = nullptr; cudaGetSymbolAddress(&pA, g_A);

    // fp16 activations: dims (K, ROWS), box (64, 128), SW128
    CUtensorMap tmA, tmA2;
    {
        unsigned long long dims[2] = {H_DIM, ROWS_CAP};
        unsigned long long strides[1] = {H_DIM * 2ull};
        unsigned box[2] = {64u, 128u};
        unsigned es[2] = {1u, 1u};
        enc(&tmA, CU_TENSOR_MAP_DATA_TYPE_FLOAT16, 2, pX, dims, strides, box, es,
            CU_TENSOR_MAP_INTERLEAVE_NONE, CU_TENSOR_MAP_SWIZZLE_128B,
            CU_TENSOR_MAP_L2_PROMOTION_L2_128B, CU_TENSOR_MAP_FLOAT_OOB_FILL_NONE);
        unsigned long long dims2[2] = {F_DIM, ROWS_CAP};
        unsigned long long strides2[1] = {F_DIM * 2ull};
        enc(&tmA2, CU_TENSOR_MAP_DATA_TYPE_FLOAT16, 2, pA, dims2, strides2, box, es,
            CU_TENSOR_MAP_INTERLEAVE_NONE, CU_TENSOR_MAP_SWIZZLE_128B,
            CU_TENSOR_MAP_L2_PROMOTION_L2_128B, CU_TENSOR_MAP_FLOAT_OOB_FILL_NONE);
    }
    // f32 weights: box (32, 64, 1), SW128
    CUtensorMap tmW1, tmW3, tmW2;
    {
        unsigned long long dims[3] = {F_DIM, H_DIM, E_EXP};
        unsigned long long strides[2] = {F_DIM * 4ull, (unsigned long long)F_DIM * H_DIM * 4ull};
        unsigned box[3] = {32u, 64u, 1u};
        unsigned es[3] = {1u, 1u, 1u};
        enc(&tmW1, CU_TENSOR_MAP_DATA_TYPE_FLOAT32, 3, (void*)w1, dims, strides, box, es,
            CU_TENSOR_MAP_INTERLEAVE_NONE, CU_TENSOR_MAP_SWIZZLE_128B,
            CU_TENSOR_MAP_L2_PROMOTION_L2_128B, CU_TENSOR_MAP_FLOAT_OOB_FILL_NONE);
        enc(&tmW3, CU_TENSOR_MAP_DATA_TYPE_FLOAT32, 3, (void*)w3, dims, strides, box, es,
            CU_TENSOR_MAP_INTERLEAVE_NONE, CU_TENSOR_MAP_SWIZZLE_128B,
            CU_TENSOR_MAP_L2_PROMOTION_L2_128B, CU_TENSOR_MAP_FLOAT_OOB_FILL_NONE);
        unsigned long long dims2[3] = {H_DIM, F_DIM, E_EXP};
        unsigned long long strides2[2] = {H_DIM * 4ull, (unsigned long long)H_DIM * F_DIM * 4ull};
        enc(&tmW2, CU_TENSOR_MAP_DATA_TYPE_FLOAT32, 3, (void*)w2, dims2, strides2, box, es,
            CU_TENSOR_MAP_INTERLEAVE_NONE, CU_TENSOR_MAP_SWIZZLE_128B,
            CU_TENSOR_MAP_L2_PROMOTION_L2_128B, CU_TENSOR_MAP_FLOAT_OOB_FILL_NONE);
    }

    cudaFuncSetAttribute(gemm13_kernel, cudaFuncAttributeMaxDynamicSharedMemorySize, SMEM13);
    cudaFuncSetAttribute(gemm2_kernel, cudaFuncAttributeMaxDynamicSharedMemorySize, SMEM2);

    gate_kernel<<<T_TOK / 8, 256>>>(x, wg);
    route_scatter_kernel<<<1, 256>>>();
    gather_kernel<<<ROWS_CAP * 512 / 256, 256>>>(x);

    dim3 g1(F_DIM / 64, MTILES);
    gemm13_kernel<<<g1, 256, SMEM13>>>(tmA, tmW1, tmW3);

    dim3 g2(H_DIM / 128, MTILES, KSPLIT);
    gemm2_kernel<<<g2, 256, SMEM2>>>(tmA2, tmW2);

    combine_kernel<<<(T_TOK * H_DIM / 4) / 256, 256>>>(out);
}